// round 1
// baseline (speedup 1.0000x reference)
#include <cuda_runtime.h>
#include <mma.h>

using namespace nvcuda;

// Problem dims (fixed)
#define BB 8
#define LL 2048
#define VV 1024
#define DD 512

// Scratch in __device__ globals (allocation rules forbid cudaMalloc)
__device__ float g_Q[BB * LL * DD];                 // 33.5 MB
__device__ float g_K[BB * LL * DD];                 // 33.5 MB
__device__ float g_V[BB * LL * DD];                 // 33.5 MB
__device__ float g_S[BB * LL * LL];                 // 134 MB (scores / probs)

// ---------------------------------------------------------------------------
// Generic tf32 WMMA GEMM:
//   C[m,n] = alpha * sum_k A[m,k] * Bmat(k,n)
//   B_KMAJOR = true : Bmat(k,n) = B[n*ldb + k]   ("NT", B stored [N,K] row-major)
//   B_KMAJOR = false: Bmat(k,n) = B[k*ldb + n]   ("NN", B stored [K,N] row-major)
// Block tile 64x64, K-chunk 32, 4 warps (2x2), each warp 32x32 via 2x2 wmma frags.
// All dims used here are multiples of the tile sizes -> no bounds checks.
// ---------------------------------------------------------------------------
template <bool B_KMAJOR>
__global__ void __launch_bounds__(128)
gemm_tf32(const float* __restrict__ A, const float* __restrict__ B,
          float* __restrict__ C, int K, int lda, int ldb, int ldc,
          long sA, long sB, long sC, float alpha)
{
    constexpr int BM = 64, BN = 64, BK = 32;
    constexpr int LDA_S  = BK + 4;   // 36 floats (144 B, 16B-multiple for wmma ldm)
    constexpr int LDB_S  = BK + 4;   // NT tile: [BN][BK]
    constexpr int LDB2_S = BN + 4;   // NN tile: [BK][BN], 68 floats (272 B)

    __shared__ float As[BM * LDA_S];         // 64*36 = 2304 floats
    __shared__ float Bs[BM * LDA_S];         // 2304 >= max(64*36, 32*68=2176)

    const float* Ab = A + (long)blockIdx.z * sA;
    const float* Bb = B + (long)blockIdx.z * sB;
    float*       Cb = C + (long)blockIdx.z * sC;

    const int m0  = blockIdx.x * BM;
    const int n0  = blockIdx.y * BN;
    const int tid = threadIdx.x;
    const int warp = tid >> 5;
    const int wm = warp >> 1;      // 0..1
    const int wn = warp & 1;       // 0..1

    wmma::fragment<wmma::accumulator, 16, 16, 8, float> acc[2][2];
#pragma unroll
    for (int i = 0; i < 2; i++)
#pragma unroll
        for (int j = 0; j < 2; j++)
            wmma::fill_fragment(acc[i][j], 0.0f);

    for (int k0 = 0; k0 < K; k0 += BK) {
        // ---- stage A tile: BM x BK = 512 float4 loads over 128 threads ----
#pragma unroll
        for (int it = 0; it < 4; it++) {
            int i   = tid + it * 128;      // 0..511
            int row = i >> 3;              // i / (BK/4)
            int c4  = (i & 7) << 2;
            float4 v = *(const float4*)(Ab + (long)(m0 + row) * lda + k0 + c4);
            float* d = &As[row * LDA_S + c4];
            d[0] = wmma::__float_to_tf32(v.x);
            d[1] = wmma::__float_to_tf32(v.y);
            d[2] = wmma::__float_to_tf32(v.z);
            d[3] = wmma::__float_to_tf32(v.w);
        }
        // ---- stage B tile ----
        if (B_KMAJOR) {
#pragma unroll
            for (int it = 0; it < 4; it++) {
                int i   = tid + it * 128;
                int row = i >> 3;
                int c4  = (i & 7) << 2;
                float4 v = *(const float4*)(Bb + (long)(n0 + row) * ldb + k0 + c4);
                float* d = &Bs[row * LDB_S + c4];
                d[0] = wmma::__float_to_tf32(v.x);
                d[1] = wmma::__float_to_tf32(v.y);
                d[2] = wmma::__float_to_tf32(v.z);
                d[3] = wmma::__float_to_tf32(v.w);
            }
        } else {
#pragma unroll
            for (int it = 0; it < 4; it++) {
                int i   = tid + it * 128;
                int row = i >> 4;              // i / (BN/4)
                int c4  = (i & 15) << 2;
                float4 v = *(const float4*)(Bb + (long)(k0 + row) * ldb + n0 + c4);
                float* d = &Bs[row * LDB2_S + c4];
                d[0] = wmma::__float_to_tf32(v.x);
                d[1] = wmma::__float_to_tf32(v.y);
                d[2] = wmma::__float_to_tf32(v.z);
                d[3] = wmma::__float_to_tf32(v.w);
            }
        }
        __syncthreads();

        // ---- compute ----
#pragma unroll
        for (int kk = 0; kk < BK; kk += 8) {
            wmma::fragment<wmma::matrix_a, 16, 16, 8, wmma::precision::tf32,
                           wmma::row_major> af[2];
#pragma unroll
            for (int i = 0; i < 2; i++)
                wmma::load_matrix_sync(af[i], &As[(wm * 32 + i * 16) * LDA_S + kk], LDA_S);

            if constexpr (B_KMAJOR) {
                wmma::fragment<wmma::matrix_b, 16, 16, 8, wmma::precision::tf32,
                               wmma::col_major> bf[2];
#pragma unroll
                for (int j = 0; j < 2; j++)
                    wmma::load_matrix_sync(bf[j], &Bs[(wn * 32 + j * 16) * LDB_S + kk], LDB_S);
#pragma unroll
                for (int i = 0; i < 2; i++)
#pragma unroll
                    for (int j = 0; j < 2; j++)
                        wmma::mma_sync(acc[i][j], af[i], bf[j], acc[i][j]);
            } else {
                wmma::fragment<wmma::matrix_b, 16, 16, 8, wmma::precision::tf32,
                               wmma::row_major> bf[2];
#pragma unroll
                for (int j = 0; j < 2; j++)
                    wmma::load_matrix_sync(bf[j], &Bs[kk * LDB2_S + wn * 32 + j * 16], LDB2_S);
#pragma unroll
                for (int i = 0; i < 2; i++)
#pragma unroll
                    for (int j = 0; j < 2; j++)
                        wmma::mma_sync(acc[i][j], af[i], bf[j], acc[i][j]);
            }
        }
        __syncthreads();
    }

    // ---- epilogue ----
#pragma unroll
    for (int i = 0; i < 2; i++)
#pragma unroll
        for (int j = 0; j < 2; j++) {
#pragma unroll
            for (int e = 0; e < acc[i][j].num_elements; e++)
                acc[i][j].x[e] *= alpha;
            wmma::store_matrix_sync(
                &Cb[(long)(m0 + wm * 32 + i * 16) * ldc + n0 + wn * 32 + j * 16],
                acc[i][j], ldc, wmma::mem_row_major);
        }
}

// ---------------------------------------------------------------------------
// Row softmax over 2048 columns, register-resident (one read + one write).
// One block of 256 threads per row; each thread owns 2 float4 = 8 values.
// ---------------------------------------------------------------------------
__global__ void __launch_bounds__(256)
softmax_rows(float* __restrict__ S)
{
    const int COLS = LL;               // 2048
    float* p = S + (long)blockIdx.x * COLS;
    const int tid  = threadIdx.x;
    const int lane = tid & 31;
    const int warp = tid >> 5;

    __shared__ float wred[8];
    __shared__ float sbcast;

    float4 r0 = ((const float4*)p)[tid];
    float4 r1 = ((const float4*)p)[tid + 256];

    // --- max ---
    float m = fmaxf(fmaxf(fmaxf(r0.x, r0.y), fmaxf(r0.z, r0.w)),
                    fmaxf(fmaxf(r1.x, r1.y), fmaxf(r1.z, r1.w)));
#pragma unroll
    for (int off = 16; off > 0; off >>= 1)
        m = fmaxf(m, __shfl_xor_sync(0xffffffffu, m, off));
    if (lane == 0) wred[warp] = m;
    __syncthreads();
    if (tid == 0) {
        float mm = wred[0];
#pragma unroll
        for (int w = 1; w < 8; w++) mm = fmaxf(mm, wred[w]);
        sbcast = mm;
    }
    __syncthreads();
    m = sbcast;
    __syncthreads();   // protect sbcast reuse below

    // --- exp + sum ---
    r0.x = __expf(r0.x - m); r0.y = __expf(r0.y - m);
    r0.z = __expf(r0.z - m); r0.w = __expf(r0.w - m);
    r1.x = __expf(r1.x - m); r1.y = __expf(r1.y - m);
    r1.z = __expf(r1.z - m); r1.w = __expf(r1.w - m);
    float s = (r0.x + r0.y + r0.z + r0.w) + (r1.x + r1.y + r1.z + r1.w);
#pragma unroll
    for (int off = 16; off > 0; off >>= 1)
        s += __shfl_xor_sync(0xffffffffu, s, off);
    if (lane == 0) wred[warp] = s;
    __syncthreads();
    if (tid == 0) {
        float ss = 0.0f;
#pragma unroll
        for (int w = 0; w < 8; w++) ss += wred[w];
        sbcast = ss;
    }
    __syncthreads();
    const float inv = 1.0f / sbcast;

    r0.x *= inv; r0.y *= inv; r0.z *= inv; r0.w *= inv;
    r1.x *= inv; r1.y *= inv; r1.z *= inv; r1.w *= inv;
    ((float4*)p)[tid]       = r0;
    ((float4*)p)[tid + 256] = r1;
}

// ---------------------------------------------------------------------------
// kernel_launch: x, Wq, Wk, Wv  ->  out [B, L, D] fp32
// ---------------------------------------------------------------------------
extern "C" void kernel_launch(void* const* d_in, const int* in_sizes, int n_in,
                              void* d_out, int out_size)
{
    (void)in_sizes; (void)n_in; (void)out_size;
    const float* x  = (const float*)d_in[0];   // [B, L, V]
    const float* Wq = (const float*)d_in[1];   // [D, V]
    const float* Wk = (const float*)d_in[2];
    const float* Wv = (const float*)d_in[3];
    float* out = (float*)d_out;                // [B, L, D]

    float *qp, *kp, *vp, *sp;
    cudaGetSymbolAddress((void**)&qp, g_Q);
    cudaGetSymbolAddress((void**)&kp, g_K);
    cudaGetSymbolAddress((void**)&vp, g_V);
    cudaGetSymbolAddress((void**)&sp, g_S);

    const int M = BB * LL;                     // 16384

    // 1) QKV projections: [16384,1024] x [512,1024]^T -> [16384,512]
    {
        dim3 grid(M / 64, DD / 64, 1);
        gemm_tf32<true><<<grid, 128>>>(x, Wq, qp, VV, VV, VV, DD, 0, 0, 0, 1.0f);
        gemm_tf32<true><<<grid, 128>>>(x, Wk, kp, VV, VV, VV, DD, 0, 0, 0, 1.0f);
        gemm_tf32<true><<<grid, 128>>>(x, Wv, vp, VV, VV, VV, DD, 0, 0, 0, 1.0f);
    }

    // 2) scores: per batch S = Q K^T / sqrt(D)   [2048,2048]
    {
        dim3 grid(LL / 64, LL / 64, BB);
        const float alpha = 0.044194173824159216f;  // 1/sqrt(512)
        gemm_tf32<true><<<grid, 128>>>(qp, kp, sp, DD, DD, DD, LL,
                                       (long)LL * DD, (long)LL * DD,
                                       (long)LL * LL, alpha);
    }

    // 3) softmax rows (in place)
    softmax_rows<<<BB * LL, 256>>>(sp);

    // 4) output: per batch O = P V   [2048,512]
    {
        dim3 grid(LL / 64, DD / 64, BB);
        gemm_tf32<false><<<grid, 128>>>(sp, vp, out, LL, LL, DD, DD,
                                        (long)LL * LL, (long)LL * DD,
                                        (long)LL * DD, 1.0f);
    }
}

// round 4
// speedup vs baseline: 2.0503x; 2.0503x over previous
#include <cuda_runtime.h>
#include <cstdint>

#define BB 8
#define LL 2048
#define VV 1024
#define DD 512

// ---------------- scratch (device globals; no allocs allowed) ----------------
__device__ float g_X [BB * LL * VV];   // tf32-rounded x
__device__ float g_Wq[DD * VV];
__device__ float g_Wk[DD * VV];
__device__ float g_Wv[DD * VV];
__device__ float g_Q [BB * LL * DD];
__device__ float g_K [BB * LL * DD];
__device__ float g_V [BB * LL * DD];
__device__ float g_Vt[BB * DD * LL];   // V transposed per batch
__device__ float g_S [BB * LL * LL];   // scores / probs

// ---------------- helpers ----------------
__device__ __forceinline__ float to_tf32(float x) {
    float r; asm("cvt.rna.tf32.f32 %0, %1;" : "=f"(r) : "f"(x)); return r;
}
__device__ __forceinline__ uint32_t smem_u32(const void* p) {
    uint32_t a;
    asm("{ .reg .u64 t; cvta.to.shared.u64 t, %1; cvt.u32.u64 %0, t; }" : "=r"(a) : "l"(p));
    return a;
}
__device__ __forceinline__ void cp_async16(uint32_t dst, const void* src) {
    asm volatile("cp.async.cg.shared.global [%0], [%1], 16;" :: "r"(dst), "l"(src));
}
__device__ __forceinline__ void cp_commit() {
    asm volatile("cp.async.commit_group;" ::: "memory");
}
__device__ __forceinline__ void cp_wait1() {
    asm volatile("cp.async.wait_group 1;" ::: "memory");
}
__device__ __forceinline__ void mma_tf32(float* c, const uint32_t* a, const uint32_t* b) {
    asm volatile(
        "mma.sync.aligned.m16n8k8.row.col.f32.tf32.tf32.f32 "
        "{%0,%1,%2,%3}, {%4,%5,%6,%7}, {%8,%9}, {%0,%1,%2,%3};"
        : "+f"(c[0]), "+f"(c[1]), "+f"(c[2]), "+f"(c[3])
        : "r"(a[0]), "r"(a[1]), "r"(a[2]), "r"(a[3]), "r"(b[0]), "r"(b[1]));
}

// ---------------- elementwise tf32 rounding pass ----------------
__global__ void round_tf32(const float* __restrict__ in, float* __restrict__ out, int n4) {
    int i = blockIdx.x * blockDim.x + threadIdx.x;
    int stride = gridDim.x * blockDim.x;
    const float4* s = (const float4*)in;
    float4*       d = (float4*)out;
    for (; i < n4; i += stride) {
        float4 v = s[i];
        v.x = to_tf32(v.x); v.y = to_tf32(v.y);
        v.z = to_tf32(v.z); v.w = to_tf32(v.w);
        d[i] = v;
    }
}

// ---------------- batched transpose V[b][l][d] -> Vt[b][d][l] ----------------
__global__ void transpose_bt(const float* __restrict__ V, float* __restrict__ Vt) {
    __shared__ float t[32][33];
    const float* Vb = V  + (size_t)blockIdx.z * LL * DD;
    float*       Tb = Vt + (size_t)blockIdx.z * DD * LL;
    int l0 = blockIdx.x * 32, d0 = blockIdx.y * 32;
    int x = threadIdx.x, y = threadIdx.y;                 // 32 x 8
#pragma unroll
    for (int i = 0; i < 32; i += 8)
        t[y + i][x] = Vb[(size_t)(l0 + y + i) * DD + d0 + x];
    __syncthreads();
#pragma unroll
    for (int i = 0; i < 32; i += 8)
        Tb[(size_t)(d0 + y + i) * LL + l0 + x] = t[x][y + i];
}

// ---------------------------------------------------------------------------
// tf32 mma.sync GEMM, NT:  C[m,n] = alpha * sum_k A[m,k] * B[n,k]
// A: [M,K] row-major (K-major), B: [N,K] row-major (K-major).
// M,N %128==0, K %32==0. 256 threads, block tile 128x128x32, warp tile 64x32,
// 3-stage cp.async pipeline. Smem XOR swizzle: word k ^ ((row&7)<<2) -> all
// fragment LDS patterns conflict-free.
// ---------------------------------------------------------------------------
#define STAGES      3
#define ATILE_B     16384                 // 128 rows * 128 B
#define STAGE_BYTES 32768                 // A + B tile
#define DYN_SMEM    (STAGES * STAGE_BYTES)

__global__ void __launch_bounds__(256, 1)
gemm_mma(const float* __restrict__ A, const float* __restrict__ B, float* __restrict__ C,
         int K, int lda, int ldb, int ldc, long sA, long sB, long sC,
         float alpha, int round_out)
{
    extern __shared__ __align__(1024) char smem[];
    const uint32_t sbase = smem_u32(smem);

    const int tid  = threadIdx.x;
    const int lane = tid & 31, wid = tid >> 5;
    const int wm = wid >> 2;          // 0..1  (64-row slab)
    const int wn = wid & 3;           // 0..3  (32-col slab)
    const int grp = lane >> 2;        // 0..7
    const int tg  = lane & 3;         // 0..3

    const float* Ab = A + (long)blockIdx.z * sA;
    const float* Bb = B + (long)blockIdx.z * sB;
    float*       Cb = C + (long)blockIdx.z * sC;
    const int m0 = blockIdx.x * 128;
    const int n0 = blockIdx.y * 128;
    const int T  = K >> 5;

    // --- stage loader: 4 iters x (1 A + 1 B) 16B cp.async per thread ---
    auto load_stage = [&](int t) {
        const int s  = t % STAGES;
        const int k0 = t << 5;
        const uint32_t st = sbase + s * STAGE_BYTES;
#pragma unroll
        for (int it = 0; it < 4; it++) {
            int i   = tid + it * 256;            // 0..1023
            int row = i >> 3;                    // 0..127
            int c4  = (i & 7) << 2;              // 0,4,...,28
            uint32_t off = (uint32_t)(row * 128) + ((((uint32_t)(c4 >> 2)) ^ (row & 7)) << 4);
            cp_async16(st + off,           Ab + (size_t)(m0 + row) * lda + k0 + c4);
            cp_async16(st + ATILE_B + off, Bb + (size_t)(n0 + row) * ldb + k0 + c4);
        }
    };

    float c[16][4];
#pragma unroll
    for (int i = 0; i < 16; i++)
#pragma unroll
        for (int j = 0; j < 4; j++) c[i][j] = 0.0f;

    load_stage(0); cp_commit();
    load_stage(1); cp_commit();

    const uint32_t swz = (uint32_t)grp << 2;     // row&7 == grp for all frag rows

    for (int t = 0; t < T; t++) {
        cp_wait1();
        __syncthreads();
        if (t + 2 < T) load_stage(t + 2);
        cp_commit();                              // empty groups keep accounting uniform

        const char* sa = smem + (t % STAGES) * STAGE_BYTES;
        const char* sb = sa + ATILE_B;

#pragma unroll
        for (int kk = 0; kk < 32; kk += 8) {
            const uint32_t kw0 = ((uint32_t)(kk + tg)     ^ swz) << 2;   // byte offset of k
            const uint32_t kw4 = ((uint32_t)(kk + tg + 4) ^ swz) << 2;

            uint32_t a[4][4];
#pragma unroll
            for (int i = 0; i < 4; i++) {
                const char* r0 = sa + (wm * 64 + i * 16 + grp) * 128;
                a[i][0] = *(const uint32_t*)(r0 + kw0);
                a[i][1] = *(const uint32_t*)(r0 + 8 * 128 + kw0);
                a[i][2] = *(const uint32_t*)(r0 + kw4);
                a[i][3] = *(const uint32_t*)(r0 + 8 * 128 + kw4);
            }
            uint32_t b[4][2];
#pragma unroll
            for (int j = 0; j < 4; j++) {
                const char* rn = sb + (wn * 32 + j * 8 + grp) * 128;
                b[j][0] = *(const uint32_t*)(rn + kw0);
                b[j][1] = *(const uint32_t*)(rn + kw4);
            }
#pragma unroll
            for (int i = 0; i < 4; i++)
#pragma unroll
                for (int j = 0; j < 4; j++)
                    mma_tf32(c[i * 4 + j], a[i], b[j]);
        }
        __syncthreads();
    }

    // --- epilogue: direct stg.64 per fragment half ---
#pragma unroll
    for (int i = 0; i < 4; i++) {
        int r = m0 + wm * 64 + i * 16 + grp;
#pragma unroll
        for (int j = 0; j < 4; j++) {
            int col = n0 + wn * 32 + j * 8 + tg * 2;
            float* cc = c[i * 4 + j];
            float2 v0 = make_float2(cc[0] * alpha, cc[1] * alpha);
            float2 v1 = make_float2(cc[2] * alpha, cc[3] * alpha);
            if (round_out) {
                v0.x = to_tf32(v0.x); v0.y = to_tf32(v0.y);
                v1.x = to_tf32(v1.x); v1.y = to_tf32(v1.y);
            }
            *(float2*)&Cb[(size_t)r * ldc + col]       = v0;
            *(float2*)&Cb[(size_t)(r + 8) * ldc + col] = v1;
        }
    }
}

// ---------------- row softmax (2048 cols), writes tf32-rounded probs ----------------
__global__ void __launch_bounds__(256)
softmax_rows(float* __restrict__ S)
{
    float* p = S + (long)blockIdx.x * LL;
    const int tid = threadIdx.x, lane = tid & 31, warp = tid >> 5;
    __shared__ float wred[8];
    __shared__ float sbcast;

    float4 r0 = ((const float4*)p)[tid];
    float4 r1 = ((const float4*)p)[tid + 256];

    float m = fmaxf(fmaxf(fmaxf(r0.x, r0.y), fmaxf(r0.z, r0.w)),
                    fmaxf(fmaxf(r1.x, r1.y), fmaxf(r1.z, r1.w)));
#pragma unroll
    for (int off = 16; off > 0; off >>= 1)
        m = fmaxf(m, __shfl_xor_sync(0xffffffffu, m, off));
    if (lane == 0) wred[warp] = m;
    __syncthreads();
    if (tid == 0) {
        float mm = wred[0];
#pragma unroll
        for (int w = 1; w < 8; w++) mm = fmaxf(mm, wred[w]);
        sbcast = mm;
    }
    __syncthreads();
    m = sbcast;
    __syncthreads();

    r0.x = __expf(r0.x - m); r0.y = __expf(r0.y - m);
    r0.z = __expf(r0.z - m); r0.w = __expf(r0.w - m);
    r1.x = __expf(r1.x - m); r1.y = __expf(r1.y - m);
    r1.z = __expf(r1.z - m); r1.w = __expf(r1.w - m);
    float s = (r0.x + r0.y + r0.z + r0.w) + (r1.x + r1.y + r1.z + r1.w);
#pragma unroll
    for (int off = 16; off > 0; off >>= 1)
        s += __shfl_xor_sync(0xffffffffu, s, off);
    if (lane == 0) wred[warp] = s;
    __syncthreads();
    if (tid == 0) {
        float ss = 0.0f;
#pragma unroll
        for (int w = 0; w < 8; w++) ss += wred[w];
        sbcast = ss;
    }
    __syncthreads();
    const float inv = 1.0f / sbcast;

    r0.x = to_tf32(r0.x * inv); r0.y = to_tf32(r0.y * inv);
    r0.z = to_tf32(r0.z * inv); r0.w = to_tf32(r0.w * inv);
    r1.x = to_tf32(r1.x * inv); r1.y = to_tf32(r1.y * inv);
    r1.z = to_tf32(r1.z * inv); r1.w = to_tf32(r1.w * inv);
    ((float4*)p)[tid]       = r0;
    ((float4*)p)[tid + 256] = r1;
}

// ---------------------------------------------------------------------------
extern "C" void kernel_launch(void* const* d_in, const int* in_sizes, int n_in,
                              void* d_out, int out_size)
{
    (void)in_sizes; (void)n_in; (void)out_size;
    const float* x  = (const float*)d_in[0];   // [B, L, V]
    const float* Wq = (const float*)d_in[1];   // [D, V]
    const float* Wk = (const float*)d_in[2];
    const float* Wv = (const float*)d_in[3];
    float* out = (float*)d_out;                // [B, L, D]

    float *xp, *wqp, *wkp, *wvp, *qp, *kp, *vp, *vtp, *sp;
    cudaGetSymbolAddress((void**)&xp,  g_X);
    cudaGetSymbolAddress((void**)&wqp, g_Wq);
    cudaGetSymbolAddress((void**)&wkp, g_Wk);
    cudaGetSymbolAddress((void**)&wvp, g_Wv);
    cudaGetSymbolAddress((void**)&qp,  g_Q);
    cudaGetSymbolAddress((void**)&kp,  g_K);
    cudaGetSymbolAddress((void**)&vp,  g_V);
    cudaGetSymbolAddress((void**)&vtp, g_Vt);
    cudaGetSymbolAddress((void**)&sp,  g_S);

    cudaFuncSetAttribute(gemm_mma, cudaFuncAttributeMaxDynamicSharedMemorySize, DYN_SMEM);

    // 0) pre-round inputs to tf32 (rna); GEMM stages then copy raw bits
    round_tf32<<<2048, 256>>>(x,  xp,  (BB * LL * VV) / 4);
    round_tf32<<<256,  256>>>(Wq, wqp, (DD * VV) / 4);
    round_tf32<<<256,  256>>>(Wk, wkp, (DD * VV) / 4);
    round_tf32<<<256,  256>>>(Wv, wvp, (DD * VV) / 4);

    // 1) projections: [16384,1024] x [512,1024]^T -> [16384,512] (tf32-rounded out)
    {
        dim3 g(BB * LL / 128, DD / 128, 1);
        gemm_mma<<<g, 256, DYN_SMEM>>>(xp, wqp, qp, VV, VV, VV, DD, 0, 0, 0, 1.0f, 1);
        gemm_mma<<<g, 256, DYN_SMEM>>>(xp, wkp, kp, VV, VV, VV, DD, 0, 0, 0, 1.0f, 1);
        gemm_mma<<<g, 256, DYN_SMEM>>>(xp, wvp, vp, VV, VV, VV, DD, 0, 0, 0, 1.0f, 1);
    }

    // 2) V -> Vt (per batch)
    transpose_bt<<<dim3(LL / 32, DD / 32, BB), dim3(32, 8)>>>(vp, vtp);

    // 3) scores: per batch S = Q K^T / sqrt(D)
    {
        dim3 g(LL / 128, LL / 128, BB);
        gemm_mma<<<g, 256, DYN_SMEM>>>(qp, kp, sp, DD, DD, DD, LL,
                                       (long)LL * DD, (long)LL * DD, (long)LL * LL,
                                       0.044194173824159216f, 0);
    }

    // 4) softmax rows (in place, rounds probs to tf32)
    softmax_rows<<<BB * LL, 256>>>(sp);

    // 5) out: per batch O = P V  (B = Vt, K-major)
    {
        dim3 g(LL / 128, DD / 128, BB);
        gemm_mma<<<g, 256, DYN_SMEM>>>(sp, vtp, out, LL, LL, LL, DD,
                                       (long)LL * LL, (long)DD * LL, (long)LL * DD,
                                       1.0f, 0);
    }
}

// round 6
// speedup vs baseline: 3.6249x; 1.7680x over previous
#include <cuda_runtime.h>
#include <cuda_fp16.h>
#include <cstdint>

#define BB 8
#define LL 2048
#define VV 1024
#define DD 512
#define NQKV 1536            // 3*DD concatenated

// ---------------- scratch (device globals; no allocs allowed) ----------------
__device__ __half g_Xh [BB * LL * VV];      // fp16 x                  (34 MB)
__device__ __half g_Wh [NQKV * VV];         // fp16 [Wq;Wk;Wv]         (3 MB)
__device__ __half g_QKV[BB * LL * NQKV];    // fp16 Q|K|V interleaved  (50 MB)
__device__ __half g_Vt [BB * DD * LL];      // fp16 V^T per batch      (17 MB)
__device__ float  g_S  [BB * LL * LL];      // fp32 scores             (134 MB)
__device__ __half g_P  [BB * LL * LL];      // fp16 probs              (67 MB)

// ---------------- helpers ----------------
__device__ __forceinline__ uint32_t smem_u32(const void* p) {
    uint32_t a;
    asm("{ .reg .u64 t; cvta.to.shared.u64 t, %1; cvt.u32.u64 %0, t; }" : "=r"(a) : "l"(p));
    return a;
}
__device__ __forceinline__ void cp_async16(uint32_t dst, const void* src) {
    asm volatile("cp.async.cg.shared.global [%0], [%1], 16;" :: "r"(dst), "l"(src));
}
__device__ __forceinline__ void cp_commit() {
    asm volatile("cp.async.commit_group;" ::: "memory");
}
__device__ __forceinline__ void cp_wait1() {
    asm volatile("cp.async.wait_group 1;" ::: "memory");
}
__device__ __forceinline__ void mma_f16(float* c, const uint32_t* a, const uint32_t* b) {
    asm volatile(
        "mma.sync.aligned.m16n8k16.row.col.f32.f16.f16.f32 "
        "{%0,%1,%2,%3}, {%4,%5,%6,%7}, {%8,%9}, {%0,%1,%2,%3};"
        : "+f"(c[0]), "+f"(c[1]), "+f"(c[2]), "+f"(c[3])
        : "r"(a[0]), "r"(a[1]), "r"(a[2]), "r"(a[3]), "r"(b[0]), "r"(b[1]));
}

// ---------------- fp32 -> fp16 conversion ----------------
__global__ void cvt_half(const float* __restrict__ in, __half* __restrict__ out, int n4) {
    int i = blockIdx.x * blockDim.x + threadIdx.x;
    int stride = gridDim.x * blockDim.x;
    const float4* s = (const float4*)in;
    __half2*      d = (__half2*)out;
    for (; i < n4; i += stride) {
        float4 v = s[i];
        d[2 * i]     = __floats2half2_rn(v.x, v.y);
        d[2 * i + 1] = __floats2half2_rn(v.z, v.w);
    }
}

// ------- transpose V slice of QKV: [b][l][1024+d] (ld NQKV) -> Vt[b][d][l] -------
__global__ void transpose_v(const __half* __restrict__ QKV, __half* __restrict__ Vt) {
    __shared__ __half2 s2[32][33];
    const __half* Vb = QKV + (size_t)blockIdx.z * LL * NQKV + 2 * DD;  // V slice
    __half*       Tb = Vt  + (size_t)blockIdx.z * DD * LL;
    int l0 = blockIdx.x * 32, d0 = blockIdx.y * 64;
    int x = threadIdx.x, y = threadIdx.y;                 // 32 x 8
#pragma unroll
    for (int i = 0; i < 32; i += 8)
        s2[y + i][x] = *(const __half2*)(Vb + (size_t)(l0 + y + i) * NQKV + d0 + 2 * x);
    __syncthreads();
#pragma unroll
    for (int i = 0; i < 64; i += 8) {
        int dl = y + i;                                   // 0..63
        __half2 v = s2[x][dl >> 1];
        Tb[(size_t)(d0 + dl) * LL + l0 + x] = (dl & 1) ? __high2half(v) : __low2half(v);
    }
}

// ---------------------------------------------------------------------------
// fp16 mma.sync GEMM, NT:  C[m,n] = alpha * sum_k A[m,k] * B[n,k]
// A: [M,K] halfs (K-major), B: [N,K] halfs (K-major). M,N %128==0, K %64==0.
// 256 threads, block tile 128x128x64, warp tile 64x32, 3-stage cp.async.
// Row = 128 B (64 halfs) -> same XOR swizzle as round 4 (conflict-free).
// out_fp16: 1 -> C is __half (ldc halfs), 0 -> C is float.
// ---------------------------------------------------------------------------
#define STAGES      3
#define ATILE_B     16384                 // 128 rows * 128 B
#define STAGE_BYTES 32768
#define DYN_SMEM    (STAGES * STAGE_BYTES)

__global__ void __launch_bounds__(256, 1)
gemm_h(const __half* __restrict__ A, const __half* __restrict__ B, void* __restrict__ C,
       int K, int lda, int ldb, int ldc, long sA, long sB, long sC,
       float alpha, int out_fp16)
{
    extern __shared__ __align__(1024) char smem[];
    const uint32_t sbase = smem_u32(smem);

    const int tid  = threadIdx.x;
    const int lane = tid & 31, wid = tid >> 5;
    const int wm = wid >> 2;          // 0..1
    const int wn = wid & 3;           // 0..3
    const int grp = lane >> 2;        // 0..7
    const int tg  = lane & 3;         // 0..3

    const __half* Ab = A + (long)blockIdx.z * sA;
    const __half* Bb = B + (long)blockIdx.z * sB;
    const int m0 = blockIdx.x * 128;
    const int n0 = blockIdx.y * 128;
    const int T  = K >> 6;

    // --- stage loader: 4 A + 4 B 16B chunks per thread ---
    auto load_stage = [&](int t) {
        const int s  = t % STAGES;
        const int k0 = t << 6;
        const uint32_t st = sbase + s * STAGE_BYTES;
#pragma unroll
        for (int it = 0; it < 4; it++) {
            int i   = tid + it * 256;            // 0..1023
            int row = i >> 3;                    // 0..127
            int ch  = i & 7;                     // 16B chunk (8 halfs)
            uint32_t off = (uint32_t)(row * 128) + ((((uint32_t)ch) ^ (row & 7)) << 4);
            cp_async16(st + off,           Ab + (size_t)(m0 + row) * lda + k0 + ch * 8);
            cp_async16(st + ATILE_B + off, Bb + (size_t)(n0 + row) * ldb + k0 + ch * 8);
        }
    };

    float c[16][4];
#pragma unroll
    for (int i = 0; i < 16; i++)
#pragma unroll
        for (int j = 0; j < 4; j++) c[i][j] = 0.0f;

    load_stage(0); cp_commit();
    load_stage(1); cp_commit();

    const uint32_t tg4 = (uint32_t)tg << 2;       // byte offset within 16B chunk

    for (int t = 0; t < T; t++) {
        cp_wait1();
        __syncthreads();
        if (t + 2 < T) load_stage(t + 2);
        cp_commit();

        const char* sa = smem + (t % STAGES) * STAGE_BYTES;
        const char* sb = sa + ATILE_B;

#pragma unroll
        for (int ks = 0; ks < 4; ks++) {          // k-step of 16 halfs
            const uint32_t c0 = (uint32_t)(ks * 2);   // chunk of k-lo

            uint32_t a[4][4];
#pragma unroll
            for (int i = 0; i < 4; i++) {
                int r  = wm * 64 + i * 16 + grp;
                const char* p0 = sa + r * 128;
                const char* p8 = p0 + 8 * 128;
                uint32_t swl = ((c0     ^ (uint32_t)(r & 7)) << 4) + tg4;
                uint32_t swh = (((c0+1) ^ (uint32_t)(r & 7)) << 4) + tg4;
                a[i][0] = *(const uint32_t*)(p0 + swl);
                a[i][1] = *(const uint32_t*)(p8 + swl);
                a[i][2] = *(const uint32_t*)(p0 + swh);
                a[i][3] = *(const uint32_t*)(p8 + swh);
            }
            uint32_t b[4][2];
#pragma unroll
            for (int j = 0; j < 4; j++) {
                int n  = wn * 32 + j * 8 + grp;
                const char* pn = sb + n * 128;
                b[j][0] = *(const uint32_t*)(pn + (((c0     ^ (uint32_t)(n & 7)) << 4) + tg4));
                b[j][1] = *(const uint32_t*)(pn + ((((c0+1) ^ (uint32_t)(n & 7)) << 4) + tg4));
            }
#pragma unroll
            for (int i = 0; i < 4; i++)
#pragma unroll
                for (int j = 0; j < 4; j++)
                    mma_f16(c[i * 4 + j], a[i], b[j]);
        }
        __syncthreads();
    }

    // --- epilogue ---
    if (out_fp16) {
        __half* Cb = (__half*)C + (long)blockIdx.z * sC;
#pragma unroll
        for (int i = 0; i < 4; i++) {
            int r = m0 + wm * 64 + i * 16 + grp;
#pragma unroll
            for (int j = 0; j < 4; j++) {
                int col = n0 + wn * 32 + j * 8 + tg * 2;
                float* cc = c[i * 4 + j];
                *(__half2*)&Cb[(size_t)r * ldc + col] =
                    __floats2half2_rn(cc[0] * alpha, cc[1] * alpha);
                *(__half2*)&Cb[(size_t)(r + 8) * ldc + col] =
                    __floats2half2_rn(cc[2] * alpha, cc[3] * alpha);
            }
        }
    } else {
        float* Cb = (float*)C + (long)blockIdx.z * sC;
#pragma unroll
        for (int i = 0; i < 4; i++) {
            int r = m0 + wm * 64 + i * 16 + grp;
#pragma unroll
            for (int j = 0; j < 4; j++) {
                int col = n0 + wn * 32 + j * 8 + tg * 2;
                float* cc = c[i * 4 + j];
                *(float2*)&Cb[(size_t)r * ldc + col] =
                    make_float2(cc[0] * alpha, cc[1] * alpha);
                *(float2*)&Cb[(size_t)(r + 8) * ldc + col] =
                    make_float2(cc[2] * alpha, cc[3] * alpha);
            }
        }
    }
}

// -------- row softmax (2048 fp32 cols) -> fp16 probs --------
__global__ void __launch_bounds__(256)
softmax_rows(const float* __restrict__ S, __half* __restrict__ P)
{
    const float* p = S + (long)blockIdx.x * LL;
    __half2*    po = (__half2*)(P + (long)blockIdx.x * LL);
    const int tid = threadIdx.x, lane = tid & 31, warp = tid >> 5;
    __shared__ float wred[8];
    __shared__ float sbcast;

    float4 r0 = ((const float4*)p)[tid];
    float4 r1 = ((const float4*)p)[tid + 256];

    float m = fmaxf(fmaxf(fmaxf(r0.x, r0.y), fmaxf(r0.z, r0.w)),
                    fmaxf(fmaxf(r1.x, r1.y), fmaxf(r1.z, r1.w)));
#pragma unroll
    for (int off = 16; off > 0; off >>= 1)
        m = fmaxf(m, __shfl_xor_sync(0xffffffffu, m, off));
    if (lane == 0) wred[warp] = m;
    __syncthreads();
    if (tid == 0) {
        float mm = wred[0];
#pragma unroll
        for (int w = 1; w < 8; w++) mm = fmaxf(mm, wred[w]);
        sbcast = mm;
    }
    __syncthreads();
    m = sbcast;
    __syncthreads();

    r0.x = __expf(r0.x - m); r0.y = __expf(r0.y - m);
    r0.z = __expf(r0.z - m); r0.w = __expf(r0.w - m);
    r1.x = __expf(r1.x - m); r1.y = __expf(r1.y - m);
    r1.z = __expf(r1.z - m); r1.w = __expf(r1.w - m);
    float s = (r0.x + r0.y + r0.z + r0.w) + (r1.x + r1.y + r1.z + r1.w);
#pragma unroll
    for (int off = 16; off > 0; off >>= 1)
        s += __shfl_xor_sync(0xffffffffu, s, off);
    if (lane == 0) wred[warp] = s;
    __syncthreads();
    if (tid == 0) {
        float ss = 0.0f;
#pragma unroll
        for (int w = 0; w < 8; w++) ss += wred[w];
        sbcast = ss;
    }
    __syncthreads();
    const float inv = 1.0f / sbcast;

    po[2 * tid]             = __floats2half2_rn(r0.x * inv, r0.y * inv);
    po[2 * tid + 1]         = __floats2half2_rn(r0.z * inv, r0.w * inv);
    po[2 * (tid + 256)]     = __floats2half2_rn(r1.x * inv, r1.y * inv);
    po[2 * (tid + 256) + 1] = __floats2half2_rn(r1.z * inv, r1.w * inv);
}

// ---------------------------------------------------------------------------
extern "C" void kernel_launch(void* const* d_in, const int* in_sizes, int n_in,
                              void* d_out, int out_size)
{
    (void)in_sizes; (void)n_in; (void)out_size;
    const float* x  = (const float*)d_in[0];   // [B, L, V]
    const float* Wq = (const float*)d_in[1];   // [D, V]
    const float* Wk = (const float*)d_in[2];
    const float* Wv = (const float*)d_in[3];
    float* out = (float*)d_out;                // [B, L, D]

    __half *xh, *wh, *qkv, *vt, *pp;
    float *sp;
    cudaGetSymbolAddress((void**)&xh,  g_Xh);
    cudaGetSymbolAddress((void**)&wh,  g_Wh);
    cudaGetSymbolAddress((void**)&qkv, g_QKV);
    cudaGetSymbolAddress((void**)&vt,  g_Vt);
    cudaGetSymbolAddress((void**)&sp,  g_S);
    cudaGetSymbolAddress((void**)&pp,  g_P);

    cudaFuncSetAttribute(gemm_h, cudaFuncAttributeMaxDynamicSharedMemorySize, DYN_SMEM);

    // 0) fp32 -> fp16 (RN; same 10-bit mantissa as tf32 path)
    cvt_half<<<2048, 256>>>(x,  xh, (BB * LL * VV) / 4);
    cvt_half<<<256,  256>>>(Wq, wh,                 (DD * VV) / 4);
    cvt_half<<<256,  256>>>(Wk, wh + DD * VV,       (DD * VV) / 4);
    cvt_half<<<256,  256>>>(Wv, wh + 2 * DD * VV,   (DD * VV) / 4);

    // 1) fused QKV projection: [16384,1024] x [1536,1024]^T -> fp16 [16384,1536]
    {
        dim3 g(BB * LL / 128, NQKV / 128, 1);
        gemm_h<<<g, 256, DYN_SMEM>>>(xh, wh, qkv, VV, VV, VV, NQKV, 0, 0, 0, 1.0f, 1);
    }

    // 2) V slice -> Vt  [b][d][l]
    transpose_v<<<dim3(LL / 32, DD / 64, BB), dim3(32, 8)>>>(qkv, vt);

    // 3) scores: S = Q K^T / sqrt(D)  (fp32 out)
    {
        dim3 g(LL / 128, LL / 128, BB);
        gemm_h<<<g, 256, DYN_SMEM>>>(qkv, qkv + DD, sp, DD, NQKV, NQKV, LL,
                                     (long)LL * NQKV, (long)LL * NQKV, (long)LL * LL,
                                     0.044194173824159216f, 0);
    }

    // 4) softmax rows -> fp16 probs
    softmax_rows<<<BB * LL, 256>>>(sp, pp);

    // 5) O = P V  (fp32 out)
    {
        dim3 g(LL / 128, DD / 128, BB);
        gemm_h<<<g, 256, DYN_SMEM>>>(pp, vt, out, LL, LL, LL, DD,
                                     (long)LL * LL, (long)DD * LL, (long)LL * DD,
                                     1.0f, 0);
    }
}

// round 7
// speedup vs baseline: 3.6873x; 1.0172x over previous
#include <cuda_runtime.h>
#include <cuda_fp16.h>
#include <cstdint>

#define BB 8
#define LL 2048
#define VV 1024
#define DD 512
#define NQKV 1536            // 3*DD concatenated

// ---------------- scratch (device globals; no allocs allowed) ----------------
__device__ __half g_Xh [BB * LL * VV];      // fp16 x                  (34 MB)
__device__ __half g_Wh [NQKV * VV];         // fp16 [Wq;Wk;Wv]         (3 MB)
__device__ __half g_QKV[BB * LL * NQKV];    // fp16 Q|K|V interleaved  (50 MB)
__device__ __half g_Vt [BB * DD * LL];      // fp16 V^T per batch      (17 MB)
__device__ __half g_E  [BB * LL * LL];      // fp16 exp(scores)        (67 MB)
__device__ float  g_inv[BB * LL];           // 1/rowsum                (64 KB)

// ---------------- helpers ----------------
__device__ __forceinline__ uint32_t smem_u32(const void* p) {
    uint32_t a;
    asm("{ .reg .u64 t; cvta.to.shared.u64 t, %1; cvt.u32.u64 %0, t; }" : "=r"(a) : "l"(p));
    return a;
}
__device__ __forceinline__ void cp_async16(uint32_t dst, const void* src) {
    asm volatile("cp.async.cg.shared.global [%0], [%1], 16;" :: "r"(dst), "l"(src));
}
__device__ __forceinline__ void cp_commit() {
    asm volatile("cp.async.commit_group;" ::: "memory");
}
__device__ __forceinline__ void cp_wait1() {
    asm volatile("cp.async.wait_group 1;" ::: "memory");
}
__device__ __forceinline__ void mma_f16(float* c, const uint32_t* a, const uint32_t* b) {
    asm volatile(
        "mma.sync.aligned.m16n8k16.row.col.f32.f16.f16.f32 "
        "{%0,%1,%2,%3}, {%4,%5,%6,%7}, {%8,%9}, {%0,%1,%2,%3};"
        : "+f"(c[0]), "+f"(c[1]), "+f"(c[2]), "+f"(c[3])
        : "r"(a[0]), "r"(a[1]), "r"(a[2]), "r"(a[3]), "r"(b[0]), "r"(b[1]));
}

// ---------------- fp32 -> fp16 conversions ----------------
__global__ void cvt_half(const float* __restrict__ in, __half* __restrict__ out, int n4) {
    int i = blockIdx.x * blockDim.x + threadIdx.x;
    int stride = gridDim.x * blockDim.x;
    const float4* s = (const float4*)in;
    __half2*      d = (__half2*)out;
    for (; i < n4; i += stride) {
        float4 v = s[i];
        d[2 * i]     = __floats2half2_rn(v.x, v.y);
        d[2 * i + 1] = __floats2half2_rn(v.z, v.w);
    }
}
// three weight matrices -> one concatenated fp16 buffer (blockIdx.y selects)
__global__ void cvt_half_w(const float* __restrict__ wq, const float* __restrict__ wk,
                           const float* __restrict__ wv, __half* __restrict__ out) {
    const int n4 = (DD * VV) / 4;
    const float* src = (blockIdx.y == 0) ? wq : (blockIdx.y == 1) ? wk : wv;
    __half2* d = (__half2*)(out + (size_t)blockIdx.y * DD * VV);
    int i = blockIdx.x * blockDim.x + threadIdx.x;
    int stride = gridDim.x * blockDim.x;
    const float4* s = (const float4*)src;
    for (; i < n4; i += stride) {
        float4 v = s[i];
        d[2 * i]     = __floats2half2_rn(v.x, v.y);
        d[2 * i + 1] = __floats2half2_rn(v.z, v.w);
    }
}

// ------- transpose V slice of QKV: [b][l][1024+d] (ld NQKV) -> Vt[b][d][l] -------
__global__ void transpose_v(const __half* __restrict__ QKV, __half* __restrict__ Vt) {
    __shared__ __half2 s2[32][33];
    const __half* Vb = QKV + (size_t)blockIdx.z * LL * NQKV + 2 * DD;  // V slice
    __half*       Tb = Vt  + (size_t)blockIdx.z * DD * LL;
    int l0 = blockIdx.x * 32, d0 = blockIdx.y * 64;
    int x = threadIdx.x, y = threadIdx.y;                 // 32 x 8
#pragma unroll
    for (int i = 0; i < 32; i += 8)
        s2[y + i][x] = *(const __half2*)(Vb + (size_t)(l0 + y + i) * NQKV + d0 + 2 * x);
    __syncthreads();
#pragma unroll
    for (int i = 0; i < 64; i += 8) {
        int dl = y + i;                                   // 0..63
        __half2 v = s2[x][dl >> 1];
        Tb[(size_t)(d0 + dl) * LL + l0 + x] = (dl & 1) ? __high2half(v) : __low2half(v);
    }
}

// -------- deterministic rowsum of E -> 1/sum --------
__global__ void __launch_bounds__(256)
rowsum_inv(const __half* __restrict__ E, float* __restrict__ inv)
{
    const __half* p = E + (size_t)blockIdx.x * LL;
    const int tid = threadIdx.x, lane = tid & 31, warp = tid >> 5;
    __shared__ float wred[8];
    uint4 v = ((const uint4*)p)[tid];                 // 8 halfs
    float s = 0.0f;
    const __half2* h = (const __half2*)&v;
#pragma unroll
    for (int q = 0; q < 4; q++) {
        float2 f = __half22float2(h[q]);
        s += f.x + f.y;
    }
#pragma unroll
    for (int off = 16; off > 0; off >>= 1)
        s += __shfl_xor_sync(0xffffffffu, s, off);
    if (lane == 0) wred[warp] = s;
    __syncthreads();
    if (tid == 0) {
        float t = 0.0f;
#pragma unroll
        for (int w = 0; w < 8; w++) t += wred[w];
        inv[blockIdx.x] = 1.0f / t;
    }
}

// ---------------------------------------------------------------------------
// fp16 mma.sync GEMM, NT:  acc[m,n] = sum_k A[m,k] * B[n,k]
// MODE 0: C fp16 = acc                    (A via cp.async)
// MODE 1: C fp16 = exp(acc * alpha)       (A via cp.async)
// MODE 2: C fp32 = acc; A scaled on load by inv[m] (A via LDG/STS, reg-staged)
// 256 threads, block tile 128x128x64, warp tile 64x32, 3-stage pipeline.
// ---------------------------------------------------------------------------
#define STAGES      3
#define ATILE_B     16384                 // 128 rows * 128 B
#define STAGE_BYTES 32768
#define DYN_SMEM    (STAGES * STAGE_BYTES)

template <int MODE>
__global__ void __launch_bounds__(256, 1)
gemm_h(const __half* __restrict__ A, const __half* __restrict__ B, void* __restrict__ C,
       const float* __restrict__ rinv,
       int K, int lda, int ldb, int ldc, long sA, long sB, long sC, float alpha)
{
    extern __shared__ __align__(1024) char smem[];
    const uint32_t sbase = smem_u32(smem);

    const int tid  = threadIdx.x;
    const int lane = tid & 31, wid = tid >> 5;
    const int wm = wid >> 2;          // 0..1
    const int wn = wid & 3;           // 0..3
    const int grp = lane >> 2;        // 0..7
    const int tg  = lane & 3;         // 0..3

    const __half* Ab = A + (long)blockIdx.z * sA;
    const __half* Bb = B + (long)blockIdx.z * sB;
    const int m0 = blockIdx.x * 128;
    const int n0 = blockIdx.y * 128;
    const int T  = K >> 6;

    // per-thread fixed A rows/chunks
    int arow[4], ach[4];
    float sc[4];
#pragma unroll
    for (int it = 0; it < 4; it++) {
        int i = tid + it * 256;
        arow[it] = i >> 3;
        ach[it]  = i & 7;
        if (MODE == 2) sc[it] = rinv[blockIdx.z * LL + m0 + arow[it]];
    }

    // --- B loader (all modes) + A cp.async loader (modes 0/1) ---
    auto load_B = [&](int t) {
        const uint32_t st = sbase + (t % STAGES) * STAGE_BYTES + ATILE_B;
        const int k0 = t << 6;
#pragma unroll
        for (int it = 0; it < 4; it++) {
            uint32_t off = (uint32_t)(arow[it] * 128) + ((((uint32_t)ach[it]) ^ (arow[it] & 7)) << 4);
            cp_async16(st + off, Bb + (size_t)(n0 + arow[it]) * ldb + k0 + ach[it] * 8);
        }
    };
    auto load_A_cp = [&](int t) {
        const uint32_t st = sbase + (t % STAGES) * STAGE_BYTES;
        const int k0 = t << 6;
#pragma unroll
        for (int it = 0; it < 4; it++) {
            uint32_t off = (uint32_t)(arow[it] * 128) + ((((uint32_t)ach[it]) ^ (arow[it] & 7)) << 4);
            cp_async16(st + off, Ab + (size_t)(m0 + arow[it]) * lda + k0 + ach[it] * 8);
        }
    };

    uint4 areg[4];
    auto ldg_A = [&](int t) {
        const int k0 = t << 6;
#pragma unroll
        for (int it = 0; it < 4; it++)
            areg[it] = *(const uint4*)(Ab + (size_t)(m0 + arow[it]) * lda + k0 + ach[it] * 8);
    };
    auto sts_A = [&](int t) {
        const uint32_t st = sbase + (t % STAGES) * STAGE_BYTES;
#pragma unroll
        for (int it = 0; it < 4; it++) {
            uint32_t w[4] = { areg[it].x, areg[it].y, areg[it].z, areg[it].w };
#pragma unroll
            for (int q = 0; q < 4; q++) {
                float2 f = __half22float2(*(__half2*)&w[q]);
                __half2 h = __floats2half2_rn(f.x * sc[it], f.y * sc[it]);
                w[q] = *(uint32_t*)&h;
            }
            uint32_t off = (uint32_t)(arow[it] * 128) + ((((uint32_t)ach[it]) ^ (arow[it] & 7)) << 4);
            *(uint4*)(smem + (st - sbase) + off) = make_uint4(w[0], w[1], w[2], w[3]);
        }
    };

    float c[16][4];
#pragma unroll
    for (int i = 0; i < 16; i++)
#pragma unroll
        for (int j = 0; j < 4; j++) c[i][j] = 0.0f;

    // --- prologue: stages 0,1 ---
    if (MODE == 2) {
        ldg_A(0); load_B(0); cp_commit(); sts_A(0);
        ldg_A(1); load_B(1); cp_commit(); sts_A(1);
        __syncthreads();                      // make prologue STS visible
    } else {
        load_A_cp(0); load_B(0); cp_commit();
        load_A_cp(1); load_B(1); cp_commit();
    }

    const uint32_t tg4 = (uint32_t)tg << 2;

    for (int t = 0; t < T; t++) {
        cp_wait1();
        __syncthreads();
        const bool pf = (t + 2 < T);
        if (pf) {
            if (MODE == 2) { ldg_A(t + 2); load_B(t + 2); }
            else           { load_A_cp(t + 2); load_B(t + 2); }
        }
        cp_commit();

        const char* sa = smem + (t % STAGES) * STAGE_BYTES;
        const char* sb = sa + ATILE_B;

#pragma unroll
        for (int ks = 0; ks < 4; ks++) {
            const uint32_t c0 = (uint32_t)(ks * 2);

            uint32_t a[4][4];
#pragma unroll
            for (int i = 0; i < 4; i++) {
                int r  = wm * 64 + i * 16 + grp;
                const char* p0 = sa + r * 128;
                const char* p8 = p0 + 8 * 128;
                uint32_t swl = ((c0       ^ (uint32_t)(r & 7)) << 4) + tg4;
                uint32_t swh = (((c0 + 1) ^ (uint32_t)(r & 7)) << 4) + tg4;
                a[i][0] = *(const uint32_t*)(p0 + swl);
                a[i][1] = *(const uint32_t*)(p8 + swl);
                a[i][2] = *(const uint32_t*)(p0 + swh);
                a[i][3] = *(const uint32_t*)(p8 + swh);
            }
            uint32_t b[4][2];
#pragma unroll
            for (int j = 0; j < 4; j++) {
                int n  = wn * 32 + j * 8 + grp;
                const char* pn = sb + n * 128;
                b[j][0] = *(const uint32_t*)(pn + (((c0       ^ (uint32_t)(n & 7)) << 4) + tg4));
                b[j][1] = *(const uint32_t*)(pn + ((((c0 + 1) ^ (uint32_t)(n & 7)) << 4) + tg4));
            }
#pragma unroll
            for (int i = 0; i < 4; i++)
#pragma unroll
                for (int j = 0; j < 4; j++)
                    mma_f16(c[i * 4 + j], a[i], b[j]);
        }

        if (MODE == 2 && pf) sts_A(t + 2);   // LDG latency hidden by MMA section
        __syncthreads();
    }

    // --- epilogue ---
    if (MODE == 2) {
        float* Cb = (float*)C + (long)blockIdx.z * sC;
#pragma unroll
        for (int i = 0; i < 4; i++) {
            int r = m0 + wm * 64 + i * 16 + grp;
#pragma unroll
            for (int j = 0; j < 4; j++) {
                int col = n0 + wn * 32 + j * 8 + tg * 2;
                float* cc = c[i * 4 + j];
                *(float2*)&Cb[(size_t)r * ldc + col]       = make_float2(cc[0], cc[1]);
                *(float2*)&Cb[(size_t)(r + 8) * ldc + col] = make_float2(cc[2], cc[3]);
            }
        }
    } else {
        __half* Cb = (__half*)C + (long)blockIdx.z * sC;
#pragma unroll
        for (int i = 0; i < 4; i++) {
            int r = m0 + wm * 64 + i * 16 + grp;
#pragma unroll
            for (int j = 0; j < 4; j++) {
                int col = n0 + wn * 32 + j * 8 + tg * 2;
                float* cc = c[i * 4 + j];
                float v0 = cc[0], v1 = cc[1], v2 = cc[2], v3 = cc[3];
                if (MODE == 1) {
                    v0 = __expf(v0 * alpha); v1 = __expf(v1 * alpha);
                    v2 = __expf(v2 * alpha); v3 = __expf(v3 * alpha);
                }
                *(__half2*)&Cb[(size_t)r * ldc + col]       = __floats2half2_rn(v0, v1);
                *(__half2*)&Cb[(size_t)(r + 8) * ldc + col] = __floats2half2_rn(v2, v3);
            }
        }
    }
}

// ---------------------------------------------------------------------------
extern "C" void kernel_launch(void* const* d_in, const int* in_sizes, int n_in,
                              void* d_out, int out_size)
{
    (void)in_sizes; (void)n_in; (void)out_size;
    const float* x  = (const float*)d_in[0];   // [B, L, V]
    const float* Wq = (const float*)d_in[1];   // [D, V]
    const float* Wk = (const float*)d_in[2];
    const float* Wv = (const float*)d_in[3];
    float* out = (float*)d_out;                // [B, L, D]

    __half *xh, *wh, *qkv, *vt, *ep;
    float *iv;
    cudaGetSymbolAddress((void**)&xh,  g_Xh);
    cudaGetSymbolAddress((void**)&wh,  g_Wh);
    cudaGetSymbolAddress((void**)&qkv, g_QKV);
    cudaGetSymbolAddress((void**)&vt,  g_Vt);
    cudaGetSymbolAddress((void**)&ep,  g_E);
    cudaGetSymbolAddress((void**)&iv,  g_inv);

    cudaFuncSetAttribute(gemm_h<0>, cudaFuncAttributeMaxDynamicSharedMemorySize, DYN_SMEM);
    cudaFuncSetAttribute(gemm_h<1>, cudaFuncAttributeMaxDynamicSharedMemorySize, DYN_SMEM);
    cudaFuncSetAttribute(gemm_h<2>, cudaFuncAttributeMaxDynamicSharedMemorySize, DYN_SMEM);

    // 0) fp32 -> fp16
    cvt_half<<<2048, 256>>>(x, xh, (BB * LL * VV) / 4);
    cvt_half_w<<<dim3(128, 3), 256>>>(Wq, Wk, Wv, wh);

    // 1) fused QKV projection -> fp16 [16384,1536]
    {
        dim3 g(BB * LL / 128, NQKV / 128, 1);
        gemm_h<0><<<g, 256, DYN_SMEM>>>(xh, wh, qkv, nullptr,
                                        VV, VV, VV, NQKV, 0, 0, 0, 1.0f);
    }

    // 2) V slice -> Vt [b][d][l]
    transpose_v<<<dim3(LL / 32, DD / 64, BB), dim3(32, 8)>>>(qkv, vt);

    // 3) E = exp(Q K^T / sqrt(D))  fp16
    {
        dim3 g(LL / 128, LL / 128, BB);
        gemm_h<1><<<g, 256, DYN_SMEM>>>(qkv, qkv + DD, ep, nullptr,
                                        DD, NQKV, NQKV, LL,
                                        (long)LL * NQKV, (long)LL * NQKV, (long)LL * LL,
                                        0.044194173824159216f);
    }

    // 4) inv rowsums (deterministic)
    rowsum_inv<<<BB * LL, 256>>>(ep, iv);

    // 5) O = (E * inv) V   fp32 out
    {
        dim3 g(LL / 128, DD / 128, BB);
        gemm_h<2><<<g, 256, DYN_SMEM>>>(ep, vt, out, iv,
                                        LL, LL, LL, DD,
                                        (long)LL * LL, (long)DD * LL, (long)LL * DD,
                                        1.0f);
    }
}

// round 8
// speedup vs baseline: 3.8955x; 1.0565x over previous
#include <cuda_runtime.h>
#include <cuda_fp16.h>
#include <cstdint>

#define BB 8
#define LL 2048
#define VV 1024
#define DD 512
#define NQKV 1536            // 3*DD concatenated
#define NTILES (LL / 128)    // 16 n-tiles in scores GEMM

// ---------------- scratch (device globals; no allocs allowed) ----------------
__device__ __half g_Xh [BB * LL * VV];      // fp16 x                  (34 MB)
__device__ __half g_Wh [NQKV * VV];         // fp16 [Wq;Wk;Wv]         (3 MB)
__device__ __half g_QKV[BB * LL * NQKV];    // fp16 Q|K|V interleaved  (50 MB)
__device__ __half g_Vt [BB * DD * LL];      // fp16 V^T per batch      (17 MB)
__device__ __half g_E  [BB * LL * LL];      // fp16 exp(scores)        (67 MB)
__device__ float  g_ps [BB * LL * NTILES];  // partial row sums        (2 MB)
__device__ float  g_inv[BB * LL];           // 1/rowsum                (64 KB)

// ---------------- helpers ----------------
__device__ __forceinline__ uint32_t smem_u32(const void* p) {
    uint32_t a;
    asm("{ .reg .u64 t; cvta.to.shared.u64 t, %1; cvt.u32.u64 %0, t; }" : "=r"(a) : "l"(p));
    return a;
}
__device__ __forceinline__ void cp_async16(uint32_t dst, const void* src) {
    asm volatile("cp.async.cg.shared.global [%0], [%1], 16;" :: "r"(dst), "l"(src));
}
__device__ __forceinline__ void cp_commit() {
    asm volatile("cp.async.commit_group;" ::: "memory");
}
__device__ __forceinline__ void cp_wait1() {
    asm volatile("cp.async.wait_group 1;" ::: "memory");
}
__device__ __forceinline__ void mma_f16(float* c, const uint32_t* a, const uint32_t* b) {
    asm volatile(
        "mma.sync.aligned.m16n8k16.row.col.f32.f16.f16.f32 "
        "{%0,%1,%2,%3}, {%4,%5,%6,%7}, {%8,%9}, {%0,%1,%2,%3};"
        : "+f"(c[0]), "+f"(c[1]), "+f"(c[2]), "+f"(c[3])
        : "r"(a[0]), "r"(a[1]), "r"(a[2]), "r"(a[3]), "r"(b[0]), "r"(b[1]));
}

// ---------------- fp32 -> fp16 conversions ----------------
__global__ void cvt_half(const float* __restrict__ in, __half* __restrict__ out, int n4) {
    int i = blockIdx.x * blockDim.x + threadIdx.x;
    int stride = gridDim.x * blockDim.x;
    const float4* s = (const float4*)in;
    __half2*      d = (__half2*)out;
    for (; i < n4; i += stride) {
        float4 v = s[i];
        d[2 * i]     = __floats2half2_rn(v.x, v.y);
        d[2 * i + 1] = __floats2half2_rn(v.z, v.w);
    }
}
__global__ void cvt_half_w(const float* __restrict__ wq, const float* __restrict__ wk,
                           const float* __restrict__ wv, __half* __restrict__ out) {
    const int n4 = (DD * VV) / 4;
    const float* src = (blockIdx.y == 0) ? wq : (blockIdx.y == 1) ? wk : wv;
    __half2* d = (__half2*)(out + (size_t)blockIdx.y * DD * VV);
    int i = blockIdx.x * blockDim.x + threadIdx.x;
    int stride = gridDim.x * blockDim.x;
    const float4* s = (const float4*)src;
    for (; i < n4; i += stride) {
        float4 v = s[i];
        d[2 * i]     = __floats2half2_rn(v.x, v.y);
        d[2 * i + 1] = __floats2half2_rn(v.z, v.w);
    }
}

// ------- transpose V slice of QKV: [b][l][1024+d] -> Vt[b][d][l], half2 I/O -------
// Tile 64(l) x 64(d), 256 threads.
__global__ void transpose_v(const __half* __restrict__ QKV, __half* __restrict__ Vt) {
    __shared__ __half2 s2[64][33];            // [l][d2]
    const __half* Vb = QKV + (size_t)blockIdx.z * LL * NQKV + 2 * DD;
    __half*       Tb = Vt  + (size_t)blockIdx.z * DD * LL;
    const int l0 = blockIdx.x * 64, d0 = blockIdx.y * 64;
    const int tid  = threadIdx.x;
    const int lane = tid & 31, w = tid >> 5;  // 8 warps

    // load: warp w, iter it -> row l = w + 8*it; lane = d2 (32 half2 = 64 d)
#pragma unroll
    for (int it = 0; it < 8; it++) {
        int l = w + 8 * it;
        s2[l][lane] = *(const __half2*)(Vb + (size_t)(l0 + l) * NQKV + d0 + 2 * lane);
    }
    __syncthreads();

    // store: warp w, iter it -> d = w + 8*it; lane = l2 (32 half2 = 64 l)
#pragma unroll
    for (int it = 0; it < 8; it++) {
        int d  = w + 8 * it;
        int c  = d >> 1;
        __half2 va = s2[2 * lane][c];
        __half2 vb = s2[2 * lane + 1][c];
        __half2 o = (d & 1) ? __halves2half2(__high2half(va), __high2half(vb))
                            : __halves2half2(__low2half(va),  __low2half(vb));
        *(__half2*)(Tb + (size_t)(d0 + d) * LL + l0 + 2 * lane) = o;
    }
}

// -------- tiny rowsum finalize: 16 partials per row -> 1/sum --------
__global__ void __launch_bounds__(256)
rowsum_finalize(const float* __restrict__ ps, float* __restrict__ inv)
{
    int row = blockIdx.x * 256 + threadIdx.x;       // 0..B*LL-1
    const float* p = ps + (size_t)row * NTILES;
    float s = 0.0f;
#pragma unroll
    for (int i = 0; i < NTILES; i++) s += p[i];
    inv[row] = 1.0f / s;
}

// ---------------------------------------------------------------------------
// fp16 mma.sync GEMM, NT:  acc[m,n] = sum_k A[m,k] * B[n,k]
// MODE 0: C fp16 = acc
// MODE 1: C fp16 = exp(acc*alpha); per-row partial sums -> ps[b][row][blockIdx.y]
// MODE 2: C fp32 = acc * rinv[row]   (epilogue scaling)
// 256 threads, block tile 128x128x64, warp tile 64x32, 3-stage cp.async.
// ---------------------------------------------------------------------------
#define STAGES      3
#define ATILE_B     16384
#define STAGE_BYTES 32768
#define DYN_SMEM    (STAGES * STAGE_BYTES)

template <int MODE>
__global__ void __launch_bounds__(256, 1)
gemm_h(const __half* __restrict__ A, const __half* __restrict__ B, void* __restrict__ C,
       const float* __restrict__ rinv, float* __restrict__ ps,
       int K, int lda, int ldb, int ldc, long sA, long sB, long sC, float alpha)
{
    extern __shared__ __align__(1024) char smem[];
    const uint32_t sbase = smem_u32(smem);

    const int tid  = threadIdx.x;
    const int lane = tid & 31, wid = tid >> 5;
    const int wm = wid >> 2;          // 0..1
    const int wn = wid & 3;           // 0..3
    const int grp = lane >> 2;        // 0..7
    const int tg  = lane & 3;         // 0..3

    const __half* Ab = A + (long)blockIdx.z * sA;
    const __half* Bb = B + (long)blockIdx.z * sB;
    const int m0 = blockIdx.x * 128;
    const int n0 = blockIdx.y * 128;
    const int T  = K >> 6;

    auto load_stage = [&](int t) {
        const int s  = t % STAGES;
        const int k0 = t << 6;
        const uint32_t st = sbase + s * STAGE_BYTES;
#pragma unroll
        for (int it = 0; it < 4; it++) {
            int i   = tid + it * 256;
            int row = i >> 3;
            int ch  = i & 7;
            uint32_t off = (uint32_t)(row * 128) + ((((uint32_t)ch) ^ (row & 7)) << 4);
            cp_async16(st + off,           Ab + (size_t)(m0 + row) * lda + k0 + ch * 8);
            cp_async16(st + ATILE_B + off, Bb + (size_t)(n0 + row) * ldb + k0 + ch * 8);
        }
    };

    float c[16][4];
#pragma unroll
    for (int i = 0; i < 16; i++)
#pragma unroll
        for (int j = 0; j < 4; j++) c[i][j] = 0.0f;

    load_stage(0); cp_commit();
    load_stage(1); cp_commit();

    const uint32_t tg4 = (uint32_t)tg << 2;

    for (int t = 0; t < T; t++) {
        cp_wait1();
        __syncthreads();
        if (t + 2 < T) load_stage(t + 2);
        cp_commit();

        const char* sa = smem + (t % STAGES) * STAGE_BYTES;
        const char* sb = sa + ATILE_B;

#pragma unroll
        for (int ks = 0; ks < 4; ks++) {
            const uint32_t c0 = (uint32_t)(ks * 2);

            uint32_t a[4][4];
#pragma unroll
            for (int i = 0; i < 4; i++) {
                int r  = wm * 64 + i * 16 + grp;
                const char* p0 = sa + r * 128;
                const char* p8 = p0 + 8 * 128;
                uint32_t swl = ((c0       ^ (uint32_t)(r & 7)) << 4) + tg4;
                uint32_t swh = (((c0 + 1) ^ (uint32_t)(r & 7)) << 4) + tg4;
                a[i][0] = *(const uint32_t*)(p0 + swl);
                a[i][1] = *(const uint32_t*)(p8 + swl);
                a[i][2] = *(const uint32_t*)(p0 + swh);
                a[i][3] = *(const uint32_t*)(p8 + swh);
            }
            uint32_t b[4][2];
#pragma unroll
            for (int j = 0; j < 4; j++) {
                int n  = wn * 32 + j * 8 + grp;
                const char* pn = sb + n * 128;
                b[j][0] = *(const uint32_t*)(pn + (((c0       ^ (uint32_t)(n & 7)) << 4) + tg4));
                b[j][1] = *(const uint32_t*)(pn + ((((c0 + 1) ^ (uint32_t)(n & 7)) << 4) + tg4));
            }
#pragma unroll
            for (int i = 0; i < 4; i++)
#pragma unroll
                for (int j = 0; j < 4; j++)
                    mma_f16(c[i * 4 + j], a[i], b[j]);
        }
        __syncthreads();
    }

    // ---------------- epilogues ----------------
    if (MODE == 2) {
        float* Cb = (float*)C + (long)blockIdx.z * sC;
#pragma unroll
        for (int i = 0; i < 4; i++) {
            int r = m0 + wm * 64 + i * 16 + grp;
            float s0 = __ldg(&rinv[blockIdx.z * LL + r]);
            float s1 = __ldg(&rinv[blockIdx.z * LL + r + 8]);
#pragma unroll
            for (int j = 0; j < 4; j++) {
                int col = n0 + wn * 32 + j * 8 + tg * 2;
                float* cc = c[i * 4 + j];
                *(float2*)&Cb[(size_t)r * ldc + col]       = make_float2(cc[0] * s0, cc[1] * s0);
                *(float2*)&Cb[(size_t)(r + 8) * ldc + col] = make_float2(cc[2] * s1, cc[3] * s1);
            }
        }
    } else if (MODE == 1) {
        __half* Cb = (__half*)C + (long)blockIdx.z * sC;
        float* part = (float*)smem;                     // [128][4] row partials
#pragma unroll
        for (int i = 0; i < 4; i++) {
            int rl = wm * 64 + i * 16 + grp;
            int r  = m0 + rl;
            float rlo = 0.0f, rhi = 0.0f;
#pragma unroll
            for (int j = 0; j < 4; j++) {
                int col = n0 + wn * 32 + j * 8 + tg * 2;
                float* cc = c[i * 4 + j];
                float v0 = __expf(cc[0] * alpha), v1 = __expf(cc[1] * alpha);
                float v2 = __expf(cc[2] * alpha), v3 = __expf(cc[3] * alpha);
                rlo += v0 + v1; rhi += v2 + v3;
                *(__half2*)&Cb[(size_t)r * ldc + col]       = __floats2half2_rn(v0, v1);
                *(__half2*)&Cb[(size_t)(r + 8) * ldc + col] = __floats2half2_rn(v2, v3);
            }
            // reduce over the 4 tg lanes (same rows, different cols)
            rlo += __shfl_xor_sync(0xffffffffu, rlo, 1);
            rlo += __shfl_xor_sync(0xffffffffu, rlo, 2);
            rhi += __shfl_xor_sync(0xffffffffu, rhi, 1);
            rhi += __shfl_xor_sync(0xffffffffu, rhi, 2);
            if (tg == 0) {
                part[rl * 4 + wn]       = rlo;
                part[(rl + 8) * 4 + wn] = rhi;
            }
        }
        __syncthreads();
        if (tid < 128) {
            float s = part[tid * 4] + part[tid * 4 + 1] + part[tid * 4 + 2] + part[tid * 4 + 3];
            ps[((size_t)blockIdx.z * LL + m0 + tid) * NTILES + blockIdx.y] = s;
        }
    } else {
        __half* Cb = (__half*)C + (long)blockIdx.z * sC;
#pragma unroll
        for (int i = 0; i < 4; i++) {
            int r = m0 + wm * 64 + i * 16 + grp;
#pragma unroll
            for (int j = 0; j < 4; j++) {
                int col = n0 + wn * 32 + j * 8 + tg * 2;
                float* cc = c[i * 4 + j];
                *(__half2*)&Cb[(size_t)r * ldc + col]       = __floats2half2_rn(cc[0], cc[1]);
                *(__half2*)&Cb[(size_t)(r + 8) * ldc + col] = __floats2half2_rn(cc[2], cc[3]);
            }
        }
    }
}

// ---------------------------------------------------------------------------
extern "C" void kernel_launch(void* const* d_in, const int* in_sizes, int n_in,
                              void* d_out, int out_size)
{
    (void)in_sizes; (void)n_in; (void)out_size;
    const float* x  = (const float*)d_in[0];   // [B, L, V]
    const float* Wq = (const float*)d_in[1];   // [D, V]
    const float* Wk = (const float*)d_in[2];
    const float* Wv = (const float*)d_in[3];
    float* out = (float*)d_out;                // [B, L, D]

    __half *xh, *wh, *qkv, *vt, *ep;
    float *iv, *psp;
    cudaGetSymbolAddress((void**)&xh,  g_Xh);
    cudaGetSymbolAddress((void**)&wh,  g_Wh);
    cudaGetSymbolAddress((void**)&qkv, g_QKV);
    cudaGetSymbolAddress((void**)&vt,  g_Vt);
    cudaGetSymbolAddress((void**)&ep,  g_E);
    cudaGetSymbolAddress((void**)&iv,  g_inv);
    cudaGetSymbolAddress((void**)&psp, g_ps);

    cudaFuncSetAttribute(gemm_h<0>, cudaFuncAttributeMaxDynamicSharedMemorySize, DYN_SMEM);
    cudaFuncSetAttribute(gemm_h<1>, cudaFuncAttributeMaxDynamicSharedMemorySize, DYN_SMEM);
    cudaFuncSetAttribute(gemm_h<2>, cudaFuncAttributeMaxDynamicSharedMemorySize, DYN_SMEM);

    // 0) fp32 -> fp16
    cvt_half<<<2048, 256>>>(x, xh, (BB * LL * VV) / 4);
    cvt_half_w<<<dim3(128, 3), 256>>>(Wq, Wk, Wv, wh);

    // 1) fused QKV projection -> fp16 [16384,1536]
    {
        dim3 g(BB * LL / 128, NQKV / 128, 1);
        gemm_h<0><<<g, 256, DYN_SMEM>>>(xh, wh, qkv, nullptr, nullptr,
                                        VV, VV, VV, NQKV, 0, 0, 0, 1.0f);
    }

    // 2) V slice -> Vt [b][d][l]
    transpose_v<<<dim3(LL / 64, DD / 64, BB), 256>>>(qkv, vt);

    // 3) E = exp(Q K^T / sqrt(D)) fp16, with fused partial row sums
    {
        dim3 g(LL / 128, LL / 128, BB);
        gemm_h<1><<<g, 256, DYN_SMEM>>>(qkv, qkv + DD, ep, nullptr, psp,
                                        DD, NQKV, NQKV, LL,
                                        (long)LL * NQKV, (long)LL * NQKV, (long)LL * LL,
                                        0.044194173824159216f);
    }

    // 4) finalize 1/rowsum (reads 1 MB of partials)
    rowsum_finalize<<<BB * LL / 256, 256>>>(psp, iv);

    // 5) O = (E V) * inv  — scaling in epilogue, fp32 out
    {
        dim3 g(LL / 128, DD / 128, BB);
        gemm_h<2><<<g, 256, DYN_SMEM>>>(ep, vt, out, iv, nullptr,
                                        LL, LL, LL, DD,
                                        (long)LL * LL, (long)DD * LL, (long)LL * DD,
                                        1.0f);
    }
}

// round 10
// speedup vs baseline: 4.3416x; 1.1145x over previous
#include <cuda_runtime.h>
#include <cuda_fp16.h>
#include <cstdint>

#define BB 8
#define LL 2048
#define VV 1024
#define DD 512
#define NQKV 1536            // 3*DD concatenated
#define NTILES (LL / 128)    // 16 n-tiles in scores GEMM

// ---------------- scratch (device globals; no allocs allowed) ----------------
__device__ __half g_Xh [BB * LL * VV];      // fp16 x                  (34 MB)
__device__ __half g_Wh [NQKV * VV];         // fp16 [Wq;Wk;Wv]         (3 MB)
__device__ __half g_QKV[BB * LL * NQKV];    // fp16 Q|K|V interleaved  (50 MB)
__device__ __half g_Vt [BB * DD * LL];      // fp16 V^T per batch      (17 MB)
__device__ __half g_E  [BB * LL * LL];      // fp16 exp(scores)        (67 MB)
__device__ float  g_ps [BB * LL * NTILES];  // partial row sums        (2 MB)
__device__ float  g_inv[BB * LL];           // 1/rowsum                (64 KB)

// ---------------- helpers ----------------
__device__ __forceinline__ uint32_t smem_u32(const void* p) {
    uint32_t a;
    asm("{ .reg .u64 t; cvta.to.shared.u64 t, %1; cvt.u32.u64 %0, t; }" : "=r"(a) : "l"(p));
    return a;
}
__device__ __forceinline__ void cp_async16(uint32_t dst, const void* src) {
    asm volatile("cp.async.cg.shared.global [%0], [%1], 16;" :: "r"(dst), "l"(src));
}
__device__ __forceinline__ void cp_commit() {
    asm volatile("cp.async.commit_group;" ::: "memory");
}
__device__ __forceinline__ void cp_wait1() {
    asm volatile("cp.async.wait_group 1;" ::: "memory");
}
__device__ __forceinline__ void mma_f16(float* c, const uint32_t* a, const uint32_t* b) {
    asm volatile(
        "mma.sync.aligned.m16n8k16.row.col.f32.f16.f16.f32 "
        "{%0,%1,%2,%3}, {%4,%5,%6,%7}, {%8,%9}, {%0,%1,%2,%3};"
        : "+f"(c[0]), "+f"(c[1]), "+f"(c[2]), "+f"(c[3])
        : "r"(a[0]), "r"(a[1]), "r"(a[2]), "r"(a[3]), "r"(b[0]), "r"(b[1]));
}
__device__ __forceinline__ void ldsm_x4(uint32_t* r, uint32_t addr) {
    asm volatile("ldmatrix.sync.aligned.m8n8.x4.shared.b16 {%0,%1,%2,%3}, [%4];"
        : "=r"(r[0]), "=r"(r[1]), "=r"(r[2]), "=r"(r[3]) : "r"(addr));
}

// ---------------- fp32 -> fp16 conversions ----------------
__global__ void cvt_half(const float* __restrict__ in, __half* __restrict__ out, int n4) {
    int i = blockIdx.x * blockDim.x + threadIdx.x;
    int stride = gridDim.x * blockDim.x;
    const float4* s = (const float4*)in;
    __half2*      d = (__half2*)out;
    for (; i < n4; i += stride) {
        float4 v = s[i];
        d[2 * i]     = __floats2half2_rn(v.x, v.y);
        d[2 * i + 1] = __floats2half2_rn(v.z, v.w);
    }
}
__global__ void cvt_half_w(const float* __restrict__ wq, const float* __restrict__ wk,
                           const float* __restrict__ wv, __half* __restrict__ out) {
    const int n4 = (DD * VV) / 4;
    const float* src = (blockIdx.y == 0) ? wq : (blockIdx.y == 1) ? wk : wv;
    __half2* d = (__half2*)(out + (size_t)blockIdx.y * DD * VV);
    int i = blockIdx.x * blockDim.x + threadIdx.x;
    int stride = gridDim.x * blockDim.x;
    const float4* s = (const float4*)src;
    for (; i < n4; i += stride) {
        float4 v = s[i];
        d[2 * i]     = __floats2half2_rn(v.x, v.y);
        d[2 * i + 1] = __floats2half2_rn(v.z, v.w);
    }
}

// ------- transpose V slice of QKV: [b][l][1024+d] -> Vt[b][d][l], half2 I/O -------
__global__ void transpose_v(const __half* __restrict__ QKV, __half* __restrict__ Vt) {
    __shared__ __half2 s2[64][33];            // [l][d2]
    const __half* Vb = QKV + (size_t)blockIdx.z * LL * NQKV + 2 * DD;
    __half*       Tb = Vt  + (size_t)blockIdx.z * DD * LL;
    const int l0 = blockIdx.x * 64, d0 = blockIdx.y * 64;
    const int tid  = threadIdx.x;
    const int lane = tid & 31, w = tid >> 5;  // 8 warps

#pragma unroll
    for (int it = 0; it < 8; it++) {
        int l = w + 8 * it;
        s2[l][lane] = *(const __half2*)(Vb + (size_t)(l0 + l) * NQKV + d0 + 2 * lane);
    }
    __syncthreads();

#pragma unroll
    for (int it = 0; it < 8; it++) {
        int d  = w + 8 * it;
        int c  = d >> 1;
        __half2 va = s2[2 * lane][c];
        __half2 vb = s2[2 * lane + 1][c];
        __half2 o = (d & 1) ? __halves2half2(__high2half(va), __high2half(vb))
                            : __halves2half2(__low2half(va),  __low2half(vb));
        *(__half2*)(Tb + (size_t)(d0 + d) * LL + l0 + 2 * lane) = o;
    }
}

// -------- tiny rowsum finalize: 16 partials per row -> 1/sum --------
__global__ void __launch_bounds__(256)
rowsum_finalize(const float* __restrict__ ps, float* __restrict__ inv)
{
    int row = blockIdx.x * 256 + threadIdx.x;       // 0..B*LL-1
    const float* p = ps + (size_t)row * NTILES;
    float s = 0.0f;
#pragma unroll
    for (int i = 0; i < NTILES; i++) s += p[i];
    inv[row] = 1.0f / s;
}

// ---------------------------------------------------------------------------
// fp16 mma.sync GEMM, NT:  acc[m,n] = sum_k A[m,k] * B[n,k]
// MODE 0: C fp16 = acc
// MODE 1: C fp16 = exp(acc*alpha); per-row partial sums -> ps
// MODE 2: C fp32 = acc * rinv[row]
// 256 threads, block tile 128x128x64, warp tile 64x32, 3-stage cp.async.
// Fragment loads via ldmatrix.x4:
//   A matrices (sel=lane>>3): row off = (sel&1)*8, k-chunk = sel>>1
//   B matrices:               row off = (sel>>1)*8, k-chunk = sel&1
// ---------------------------------------------------------------------------
#define STAGES      3
#define ATILE_B     16384
#define STAGE_BYTES 32768
#define DYN_SMEM    (STAGES * STAGE_BYTES)

template <int MODE>
__global__ void __launch_bounds__(256, 1)
gemm_h(const __half* __restrict__ A, const __half* __restrict__ B, void* __restrict__ C,
       const float* __restrict__ rinv, float* __restrict__ ps,
       int K, int lda, int ldb, int ldc, long sA, long sB, long sC, float alpha)
{
    extern __shared__ __align__(1024) char smem[];
    const uint32_t sbase = smem_u32(smem);

    const int tid  = threadIdx.x;
    const int lane = tid & 31, wid = tid >> 5;
    const int wm = wid >> 2;          // 0..1
    const int wn = wid & 3;           // 0..3
    const int grp = lane >> 2;        // 0..7
    const int tg  = lane & 3;         // 0..3

    const __half* Ab = A + (long)blockIdx.z * sA;
    const __half* Bb = B + (long)blockIdx.z * sB;
    const int m0 = blockIdx.x * 128;
    const int n0 = blockIdx.y * 128;
    const int T  = K >> 6;

    auto load_stage = [&](int t) {
        const int s  = t % STAGES;
        const int k0 = t << 6;
        const uint32_t st = sbase + s * STAGE_BYTES;
#pragma unroll
        for (int it = 0; it < 4; it++) {
            int i   = tid + it * 256;
            int row = i >> 3;
            int ch  = i & 7;
            uint32_t off = (uint32_t)(row * 128) + ((((uint32_t)ch) ^ (row & 7)) << 4);
            cp_async16(st + off,           Ab + (size_t)(m0 + row) * lda + k0 + ch * 8);
            cp_async16(st + ATILE_B + off, Bb + (size_t)(n0 + row) * ldb + k0 + ch * 8);
        }
    };

    float c[16][4];
#pragma unroll
    for (int i = 0; i < 16; i++)
#pragma unroll
        for (int j = 0; j < 4; j++) c[i][j] = 0.0f;

    load_stage(0); cp_commit();
    load_stage(1); cp_commit();

    // --- ldmatrix per-thread invariant addresses ---
    const int sel   = lane >> 3;        // which 8x8 matrix this lane addresses
    const int rr    = lane & 7;
    const int selhi = sel >> 1, sello = sel & 1;

    uint32_t aRow[4];                   // A: m0->(r,klo) m1->(r+8,klo) m2->(r,khi) m3->(r+8,khi)
#pragma unroll
    for (int i = 0; i < 4; i++)
        aRow[i] = (uint32_t)((wm * 64 + i * 16 + (sello << 3) + rr) * 128);
    uint32_t bRow[2];                   // B: m0->(n,klo) m1->(n,khi) m2->(n+8,klo) m3->(n+8,khi)
#pragma unroll
    for (int jj = 0; jj < 2; jj++)
        bRow[jj] = (uint32_t)(ATILE_B + (wn * 32 + jj * 16 + (selhi << 3) + rr) * 128);

    for (int t = 0; t < T; t++) {
        cp_wait1();
        __syncthreads();
        if (t + 2 < T) load_stage(t + 2);
        cp_commit();

        const uint32_t sa32 = sbase + (t % STAGES) * STAGE_BYTES;

#pragma unroll
        for (int ks = 0; ks < 4; ks++) {
            // FIX vs round 9: A chunk uses selhi, B chunk uses sello.
            const uint32_t achS = ((uint32_t)(2 * ks + selhi) ^ (uint32_t)rr) << 4;
            const uint32_t bchS = ((uint32_t)(2 * ks + sello) ^ (uint32_t)rr) << 4;

            uint32_t a[4][4];
#pragma unroll
            for (int i = 0; i < 4; i++)
                ldsm_x4(a[i], sa32 + aRow[i] + achS);

            uint32_t b[8];
            ldsm_x4(&b[0], sa32 + bRow[0] + bchS);   // n-frags 0,1 (klo/khi pairs)
            ldsm_x4(&b[4], sa32 + bRow[1] + bchS);   // n-frags 2,3

#pragma unroll
            for (int i = 0; i < 4; i++)
#pragma unroll
                for (int j = 0; j < 4; j++)
                    mma_f16(c[i * 4 + j], a[i], &b[j * 2]);
        }
        __syncthreads();
    }

    // ---------------- epilogues ----------------
    if (MODE == 2) {
        float* Cb = (float*)C + (long)blockIdx.z * sC;
#pragma unroll
        for (int i = 0; i < 4; i++) {
            int r = m0 + wm * 64 + i * 16 + grp;
            float s0 = __ldg(&rinv[blockIdx.z * LL + r]);
            float s1 = __ldg(&rinv[blockIdx.z * LL + r + 8]);
#pragma unroll
            for (int j = 0; j < 4; j++) {
                int col = n0 + wn * 32 + j * 8 + tg * 2;
                float* cc = c[i * 4 + j];
                *(float2*)&Cb[(size_t)r * ldc + col]       = make_float2(cc[0] * s0, cc[1] * s0);
                *(float2*)&Cb[(size_t)(r + 8) * ldc + col] = make_float2(cc[2] * s1, cc[3] * s1);
            }
        }
    } else if (MODE == 1) {
        __half* Cb = (__half*)C + (long)blockIdx.z * sC;
        float* part = (float*)smem;                     // [128][4] row partials
#pragma unroll
        for (int i = 0; i < 4; i++) {
            int rl = wm * 64 + i * 16 + grp;
            int r  = m0 + rl;
            float rlo = 0.0f, rhi = 0.0f;
#pragma unroll
            for (int j = 0; j < 4; j++) {
                int col = n0 + wn * 32 + j * 8 + tg * 2;
                float* cc = c[i * 4 + j];
                float v0 = __expf(cc[0] * alpha), v1 = __expf(cc[1] * alpha);
                float v2 = __expf(cc[2] * alpha), v3 = __expf(cc[3] * alpha);
                rlo += v0 + v1; rhi += v2 + v3;
                *(__half2*)&Cb[(size_t)r * ldc + col]       = __floats2half2_rn(v0, v1);
                *(__half2*)&Cb[(size_t)(r + 8) * ldc + col] = __floats2half2_rn(v2, v3);
            }
            rlo += __shfl_xor_sync(0xffffffffu, rlo, 1);
            rlo += __shfl_xor_sync(0xffffffffu, rlo, 2);
            rhi += __shfl_xor_sync(0xffffffffu, rhi, 1);
            rhi += __shfl_xor_sync(0xffffffffu, rhi, 2);
            if (tg == 0) {
                part[rl * 4 + wn]       = rlo;
                part[(rl + 8) * 4 + wn] = rhi;
            }
        }
        __syncthreads();
        if (tid < 128) {
            float s = part[tid * 4] + part[tid * 4 + 1] + part[tid * 4 + 2] + part[tid * 4 + 3];
            ps[((size_t)blockIdx.z * LL + m0 + tid) * NTILES + blockIdx.y] = s;
        }
    } else {
        __half* Cb = (__half*)C + (long)blockIdx.z * sC;
#pragma unroll
        for (int i = 0; i < 4; i++) {
            int r = m0 + wm * 64 + i * 16 + grp;
#pragma unroll
            for (int j = 0; j < 4; j++) {
                int col = n0 + wn * 32 + j * 8 + tg * 2;
                float* cc = c[i * 4 + j];
                *(__half2*)&Cb[(size_t)r * ldc + col]       = __floats2half2_rn(cc[0], cc[1]);
                *(__half2*)&Cb[(size_t)(r + 8) * ldc + col] = __floats2half2_rn(cc[2], cc[3]);
            }
        }
    }
}

// ---------------------------------------------------------------------------
extern "C" void kernel_launch(void* const* d_in, const int* in_sizes, int n_in,
                              void* d_out, int out_size)
{
    (void)in_sizes; (void)n_in; (void)out_size;
    const float* x  = (const float*)d_in[0];   // [B, L, V]
    const float* Wq = (const float*)d_in[1];   // [D, V]
    const float* Wk = (const float*)d_in[2];
    const float* Wv = (const float*)d_in[3];
    float* out = (float*)d_out;                // [B, L, D]

    __half *xh, *wh, *qkv, *vt, *ep;
    float *iv, *psp;
    cudaGetSymbolAddress((void**)&xh,  g_Xh);
    cudaGetSymbolAddress((void**)&wh,  g_Wh);
    cudaGetSymbolAddress((void**)&qkv, g_QKV);
    cudaGetSymbolAddress((void**)&vt,  g_Vt);
    cudaGetSymbolAddress((void**)&ep,  g_E);
    cudaGetSymbolAddress((void**)&iv,  g_inv);
    cudaGetSymbolAddress((void**)&psp, g_ps);

    cudaFuncSetAttribute(gemm_h<0>, cudaFuncAttributeMaxDynamicSharedMemorySize, DYN_SMEM);
    cudaFuncSetAttribute(gemm_h<1>, cudaFuncAttributeMaxDynamicSharedMemorySize, DYN_SMEM);
    cudaFuncSetAttribute(gemm_h<2>, cudaFuncAttributeMaxDynamicSharedMemorySize, DYN_SMEM);

    // 0) fp32 -> fp16
    cvt_half<<<2048, 256>>>(x, xh, (BB * LL * VV) / 4);
    cvt_half_w<<<dim3(128, 3), 256>>>(Wq, Wk, Wv, wh);

    // 1) fused QKV projection -> fp16 [16384,1536]
    {
        dim3 g(BB * LL / 128, NQKV / 128, 1);
        gemm_h<0><<<g, 256, DYN_SMEM>>>(xh, wh, qkv, nullptr, nullptr,
                                        VV, VV, VV, NQKV, 0, 0, 0, 1.0f);
    }

    // 2) V slice -> Vt [b][d][l]
    transpose_v<<<dim3(LL / 64, DD / 64, BB), 256>>>(qkv, vt);

    // 3) E = exp(Q K^T / sqrt(D)) fp16, with fused partial row sums
    {
        dim3 g(LL / 128, LL / 128, BB);
        gemm_h<1><<<g, 256, DYN_SMEM>>>(qkv, qkv + DD, ep, nullptr, psp,
                                        DD, NQKV, NQKV, LL,
                                        (long)LL * NQKV, (long)LL * NQKV, (long)LL * LL,
                                        0.044194173824159216f);
    }

    // 4) finalize 1/rowsum
    rowsum_finalize<<<BB * LL / 256, 256>>>(psp, iv);

    // 5) O = (E V) * inv
    {
        dim3 g(LL / 128, DD / 128, BB);
        gemm_h<2><<<g, 256, DYN_SMEM>>>(ep, vt, out, iv, nullptr,
                                        LL, LL, LL, DD,
                                        (long)LL * LL, (long)DD * LL, (long)LL * DD,
                                        1.0f);
    }
}

// round 11
// speedup vs baseline: 4.4535x; 1.0258x over previous
#include <cuda_runtime.h>
#include <cuda_fp16.h>
#include <cstdint>

#define BB 8
#define LL 2048
#define VV 1024
#define DD 512
#define NQKV 1536            // 3*DD concatenated
#define NTILES (LL / 128)    // 16 n-tiles in scores GEMM

// ---------------- scratch (device globals; no allocs allowed) ----------------
__device__ __half g_Xh [BB * LL * VV];      // fp16 x                  (34 MB)
__device__ __half g_Wh [NQKV * VV];         // fp16 [Wq;Wk;Wv]         (3 MB)
__device__ __half g_QKV[BB * LL * NQKV];    // fp16 Q|K|V interleaved  (50 MB)
__device__ __half g_Vt [BB * DD * LL];      // fp16 V^T per batch      (17 MB)
__device__ __half g_E  [BB * LL * LL];      // fp16 exp(scores)        (67 MB)
__device__ float  g_ps [BB * LL * NTILES];  // partial row sums        (2 MB)

// ---------------- helpers ----------------
__device__ __forceinline__ uint32_t smem_u32(const void* p) {
    uint32_t a;
    asm("{ .reg .u64 t; cvta.to.shared.u64 t, %1; cvt.u32.u64 %0, t; }" : "=r"(a) : "l"(p));
    return a;
}
__device__ __forceinline__ void cp_async16(uint32_t dst, const void* src) {
    asm volatile("cp.async.cg.shared.global [%0], [%1], 16;" :: "r"(dst), "l"(src));
}
__device__ __forceinline__ void cp_commit() {
    asm volatile("cp.async.commit_group;" ::: "memory");
}
__device__ __forceinline__ void cp_wait2() {
    asm volatile("cp.async.wait_group 2;" ::: "memory");
}
__device__ __forceinline__ void mma_f16(float* c, const uint32_t* a, const uint32_t* b) {
    asm volatile(
        "mma.sync.aligned.m16n8k16.row.col.f32.f16.f16.f32 "
        "{%0,%1,%2,%3}, {%4,%5,%6,%7}, {%8,%9}, {%0,%1,%2,%3};"
        : "+f"(c[0]), "+f"(c[1]), "+f"(c[2]), "+f"(c[3])
        : "r"(a[0]), "r"(a[1]), "r"(a[2]), "r"(a[3]), "r"(b[0]), "r"(b[1]));
}
__device__ __forceinline__ void ldsm_x4(uint32_t* r, uint32_t addr) {
    asm volatile("ldmatrix.sync.aligned.m8n8.x4.shared.b16 {%0,%1,%2,%3}, [%4];"
        : "=r"(r[0]), "=r"(r[1]), "=r"(r[2]), "=r"(r[3]) : "r"(addr));
}

// ---------------- fp32 -> fp16 conversions ----------------
__global__ void cvt_half(const float* __restrict__ in, __half* __restrict__ out, int n4) {
    int i = blockIdx.x * blockDim.x + threadIdx.x;
    int stride = gridDim.x * blockDim.x;
    const float4* s = (const float4*)in;
    __half2*      d = (__half2*)out;
    for (; i < n4; i += stride) {
        float4 v = s[i];
        d[2 * i]     = __floats2half2_rn(v.x, v.y);
        d[2 * i + 1] = __floats2half2_rn(v.z, v.w);
    }
}
__global__ void cvt_half_w(const float* __restrict__ wq, const float* __restrict__ wk,
                           const float* __restrict__ wv, __half* __restrict__ out) {
    const int n4 = (DD * VV) / 4;
    const float* src = (blockIdx.y == 0) ? wq : (blockIdx.y == 1) ? wk : wv;
    __half2* d = (__half2*)(out + (size_t)blockIdx.y * DD * VV);
    int i = blockIdx.x * blockDim.x + threadIdx.x;
    int stride = gridDim.x * blockDim.x;
    const float4* s = (const float4*)src;
    for (; i < n4; i += stride) {
        float4 v = s[i];
        d[2 * i]     = __floats2half2_rn(v.x, v.y);
        d[2 * i + 1] = __floats2half2_rn(v.z, v.w);
    }
}

// ------- transpose V slice of QKV: [b][l][1024+d] -> Vt[b][d][l], half2 I/O -------
__global__ void transpose_v(const __half* __restrict__ QKV, __half* __restrict__ Vt) {
    __shared__ __half2 s2[64][33];            // [l][d2]
    const __half* Vb = QKV + (size_t)blockIdx.z * LL * NQKV + 2 * DD;
    __half*       Tb = Vt  + (size_t)blockIdx.z * DD * LL;
    const int l0 = blockIdx.x * 64, d0 = blockIdx.y * 64;
    const int tid  = threadIdx.x;
    const int lane = tid & 31, w = tid >> 5;  // 8 warps

#pragma unroll
    for (int it = 0; it < 8; it++) {
        int l = w + 8 * it;
        s2[l][lane] = *(const __half2*)(Vb + (size_t)(l0 + l) * NQKV + d0 + 2 * lane);
    }
    __syncthreads();

#pragma unroll
    for (int it = 0; it < 8; it++) {
        int d  = w + 8 * it;
        int c  = d >> 1;
        __half2 va = s2[2 * lane][c];
        __half2 vb = s2[2 * lane + 1][c];
        __half2 o = (d & 1) ? __halves2half2(__high2half(va), __high2half(vb))
                            : __halves2half2(__low2half(va),  __low2half(vb));
        *(__half2*)(Tb + (size_t)(d0 + d) * LL + l0 + 2 * lane) = o;
    }
}

// ---------------------------------------------------------------------------
// fp16 mma.sync GEMM, NT:  acc[m,n] = sum_k A[m,k] * B[n,k]
// MODE 0: C fp16 = acc
// MODE 1: C fp16 = exp(acc*alpha); per-row partial sums -> ps
// MODE 2: C fp32 = acc * inv(row);  inv computed in prologue from ps partials
// 256 threads, block tile 128x128x64, warp tile 64x32.
// 4-stage cp.async pipeline, prefetch distance 3, ONE __syncthreads per iter
// (write target stage == stage read at t-1, protected by the top sync).
// ---------------------------------------------------------------------------
#define STAGES      4
#define ATILE_B     16384
#define STAGE_BYTES 32768
#define DYN_SMEM    (STAGES * STAGE_BYTES)   // 131072 B

template <int MODE>
__global__ void __launch_bounds__(256, 1)
gemm_h(const __half* __restrict__ A, const __half* __restrict__ B, void* __restrict__ C,
       float* __restrict__ ps,
       int K, int lda, int ldb, int ldc, long sA, long sB, long sC, float alpha)
{
    extern __shared__ __align__(1024) char smem[];
    __shared__ float s_inv[128];
    const uint32_t sbase = smem_u32(smem);

    const int tid  = threadIdx.x;
    const int lane = tid & 31, wid = tid >> 5;
    const int wm = wid >> 2;          // 0..1
    const int wn = wid & 3;           // 0..3
    const int grp = lane >> 2;        // 0..7
    const int tg  = lane & 3;         // 0..3

    const __half* Ab = A + (long)blockIdx.z * sA;
    const __half* Bb = B + (long)blockIdx.z * sB;
    const int m0 = blockIdx.x * 128;
    const int n0 = blockIdx.y * 128;
    const int T  = K >> 6;

    // MODE 2: finalize 1/rowsum for this CTA's 128 rows (same add order as before)
    if (MODE == 2 && tid < 128) {
        const float* p = ps + ((size_t)blockIdx.z * LL + m0 + tid) * NTILES;
        float s = 0.0f;
#pragma unroll
        for (int i = 0; i < NTILES; i++) s += p[i];
        s_inv[tid] = 1.0f / s;
    }

    auto load_stage = [&](int t) {
        const int s  = t % STAGES;
        const int k0 = t << 6;
        const uint32_t st = sbase + s * STAGE_BYTES;
#pragma unroll
        for (int it = 0; it < 4; it++) {
            int i   = tid + it * 256;
            int row = i >> 3;
            int ch  = i & 7;
            uint32_t off = (uint32_t)(row * 128) + ((((uint32_t)ch) ^ (row & 7)) << 4);
            cp_async16(st + off,           Ab + (size_t)(m0 + row) * lda + k0 + ch * 8);
            cp_async16(st + ATILE_B + off, Bb + (size_t)(n0 + row) * ldb + k0 + ch * 8);
        }
    };

    float c[16][4];
#pragma unroll
    for (int i = 0; i < 16; i++)
#pragma unroll
        for (int j = 0; j < 4; j++) c[i][j] = 0.0f;

    load_stage(0); cp_commit();
    load_stage(1); cp_commit();
    load_stage(2); cp_commit();

    // --- ldmatrix per-thread invariant addresses ---
    const int sel   = lane >> 3;        // which 8x8 matrix this lane addresses
    const int rr    = lane & 7;
    const int selhi = sel >> 1, sello = sel & 1;

    uint32_t aRow[4];                   // A: m0->(r,klo) m1->(r+8,klo) m2->(r,khi) m3->(r+8,khi)
#pragma unroll
    for (int i = 0; i < 4; i++)
        aRow[i] = (uint32_t)((wm * 64 + i * 16 + (sello << 3) + rr) * 128);
    uint32_t bRow[2];                   // B: m0->(n,klo) m1->(n,khi) m2->(n+8,klo) m3->(n+8,khi)
#pragma unroll
    for (int jj = 0; jj < 2; jj++)
        bRow[jj] = (uint32_t)(ATILE_B + (wn * 32 + jj * 16 + (selhi << 3) + rr) * 128);

    for (int t = 0; t < T; t++) {
        cp_wait2();
        __syncthreads();                // single barrier per iteration
        if (t + 3 < T) load_stage(t + 3);
        cp_commit();

        const uint32_t sa32 = sbase + (t % STAGES) * STAGE_BYTES;

#pragma unroll
        for (int ks = 0; ks < 4; ks++) {
            const uint32_t achS = ((uint32_t)(2 * ks + selhi) ^ (uint32_t)rr) << 4;
            const uint32_t bchS = ((uint32_t)(2 * ks + sello) ^ (uint32_t)rr) << 4;

            uint32_t a[4][4];
#pragma unroll
            for (int i = 0; i < 4; i++)
                ldsm_x4(a[i], sa32 + aRow[i] + achS);

            uint32_t b[8];
            ldsm_x4(&b[0], sa32 + bRow[0] + bchS);   // n-frags 0,1
            ldsm_x4(&b[4], sa32 + bRow[1] + bchS);   // n-frags 2,3

#pragma unroll
            for (int i = 0; i < 4; i++)
#pragma unroll
                for (int j = 0; j < 4; j++)
                    mma_f16(c[i * 4 + j], a[i], &b[j * 2]);
        }
        // no trailing sync: next iter's writes target stage (t+4)%4 == stage
        // read at iter t+1-1 = t ... protected by next iteration's top sync.
    }

    // ---------------- epilogues ----------------
    if (MODE == 2) {
        float* Cb = (float*)C + (long)blockIdx.z * sC;
#pragma unroll
        for (int i = 0; i < 4; i++) {
            int rl = wm * 64 + i * 16 + grp;
            int r  = m0 + rl;
            float s0 = s_inv[rl];
            float s1 = s_inv[rl + 8];
#pragma unroll
            for (int j = 0; j < 4; j++) {
                int col = n0 + wn * 32 + j * 8 + tg * 2;
                float* cc = c[i * 4 + j];
                *(float2*)&Cb[(size_t)r * ldc + col]       = make_float2(cc[0] * s0, cc[1] * s0);
                *(float2*)&Cb[(size_t)(r + 8) * ldc + col] = make_float2(cc[2] * s1, cc[3] * s1);
            }
        }
    } else if (MODE == 1) {
        __syncthreads();                // smem reuse: all ldmatrix of last stage done
        __half* Cb = (__half*)C + (long)blockIdx.z * sC;
        float* part = (float*)smem;     // [128][4] row partials
#pragma unroll
        for (int i = 0; i < 4; i++) {
            int rl = wm * 64 + i * 16 + grp;
            int r  = m0 + rl;
            float rlo = 0.0f, rhi = 0.0f;
#pragma unroll
            for (int j = 0; j < 4; j++) {
                int col = n0 + wn * 32 + j * 8 + tg * 2;
                float* cc = c[i * 4 + j];
                float v0 = __expf(cc[0] * alpha), v1 = __expf(cc[1] * alpha);
                float v2 = __expf(cc[2] * alpha), v3 = __expf(cc[3] * alpha);
                rlo += v0 + v1; rhi += v2 + v3;
                *(__half2*)&Cb[(size_t)r * ldc + col]       = __floats2half2_rn(v0, v1);
                *(__half2*)&Cb[(size_t)(r + 8) * ldc + col] = __floats2half2_rn(v2, v3);
            }
            rlo += __shfl_xor_sync(0xffffffffu, rlo, 1);
            rlo += __shfl_xor_sync(0xffffffffu, rlo, 2);
            rhi += __shfl_xor_sync(0xffffffffu, rhi, 1);
            rhi += __shfl_xor_sync(0xffffffffu, rhi, 2);
            if (tg == 0) {
                part[rl * 4 + wn]       = rlo;
                part[(rl + 8) * 4 + wn] = rhi;
            }
        }
        __syncthreads();
        if (tid < 128) {
            float s = part[tid * 4] + part[tid * 4 + 1] + part[tid * 4 + 2] + part[tid * 4 + 3];
            ps[((size_t)blockIdx.z * LL + m0 + tid) * NTILES + blockIdx.y] = s;
        }
    } else {
        __half* Cb = (__half*)C + (long)blockIdx.z * sC;
#pragma unroll
        for (int i = 0; i < 4; i++) {
            int r = m0 + wm * 64 + i * 16 + grp;
#pragma unroll
            for (int j = 0; j < 4; j++) {
                int col = n0 + wn * 32 + j * 8 + tg * 2;
                float* cc = c[i * 4 + j];
                *(__half2*)&Cb[(size_t)r * ldc + col]       = __floats2half2_rn(cc[0], cc[1]);
                *(__half2*)&Cb[(size_t)(r + 8) * ldc + col] = __floats2half2_rn(cc[2], cc[3]);
            }
        }
    }
}

// ---------------------------------------------------------------------------
extern "C" void kernel_launch(void* const* d_in, const int* in_sizes, int n_in,
                              void* d_out, int out_size)
{
    (void)in_sizes; (void)n_in; (void)out_size;
    const float* x  = (const float*)d_in[0];   // [B, L, V]
    const float* Wq = (const float*)d_in[1];   // [D, V]
    const float* Wk = (const float*)d_in[2];
    const float* Wv = (const float*)d_in[3];
    float* out = (float*)d_out;                // [B, L, D]

    __half *xh, *wh, *qkv, *vt, *ep;
    float *psp;
    cudaGetSymbolAddress((void**)&xh,  g_Xh);
    cudaGetSymbolAddress((void**)&wh,  g_Wh);
    cudaGetSymbolAddress((void**)&qkv, g_QKV);
    cudaGetSymbolAddress((void**)&vt,  g_Vt);
    cudaGetSymbolAddress((void**)&ep,  g_E);
    cudaGetSymbolAddress((void**)&psp, g_ps);

    cudaFuncSetAttribute(gemm_h<0>, cudaFuncAttributeMaxDynamicSharedMemorySize, DYN_SMEM);
    cudaFuncSetAttribute(gemm_h<1>, cudaFuncAttributeMaxDynamicSharedMemorySize, DYN_SMEM);
    cudaFuncSetAttribute(gemm_h<2>, cudaFuncAttributeMaxDynamicSharedMemorySize, DYN_SMEM);

    // 0) fp32 -> fp16
    cvt_half<<<2048, 256>>>(x, xh, (BB * LL * VV) / 4);
    cvt_half_w<<<dim3(128, 3), 256>>>(Wq, Wk, Wv, wh);

    // 1) fused QKV projection -> fp16 [16384,1536]
    {
        dim3 g(BB * LL / 128, NQKV / 128, 1);
        gemm_h<0><<<g, 256, DYN_SMEM>>>(xh, wh, qkv, nullptr,
                                        VV, VV, VV, NQKV, 0, 0, 0, 1.0f);
    }

    // 2) V slice -> Vt [b][d][l]
    transpose_v<<<dim3(LL / 64, DD / 64, BB), 256>>>(qkv, vt);

    // 3) E = exp(Q K^T / sqrt(D)) fp16, with fused partial row sums
    {
        dim3 g(LL / 128, LL / 128, BB);
        gemm_h<1><<<g, 256, DYN_SMEM>>>(qkv, qkv + DD, ep, psp,
                                        DD, NQKV, NQKV, LL,
                                        (long)LL * NQKV, (long)LL * NQKV, (long)LL * LL,
                                        0.044194173824159216f);
    }

    // 4) O = (E V) * inv — rowsum finalize fused into PV prologue
    {
        dim3 g(LL / 128, DD / 128, BB);
        gemm_h<2><<<g, 256, DYN_SMEM>>>(ep, vt, out, psp,
                                        LL, LL, LL, DD,
                                        (long)LL * LL, (long)DD * LL, (long)LL * DD,
                                        1.0f);
    }
}

// round 13
// speedup vs baseline: 4.6939x; 1.0540x over previous
#include <cuda_runtime.h>
#include <cuda_fp16.h>
#include <cstdint>

#define BB 8
#define LL 2048
#define VV 1024
#define DD 512
#define NQKV 1536            // 3*DD concatenated
#define NTILES (LL / 128)    // 16 n-tiles in scores GEMM

// ---------------- scratch (device globals; no allocs allowed) ----------------
__device__ __half g_Xh [BB * LL * VV];      // fp16 x                  (34 MB)
__device__ __half g_Wh [NQKV * VV];         // fp16 [Wq;Wk;Wv]         (3 MB)
__device__ __half g_QKV[BB * LL * NQKV];    // fp16 Q|K|V interleaved  (50 MB)
__device__ __half g_Vt [BB * DD * LL];      // fp16 V^T per batch      (17 MB)
__device__ __half g_E  [BB * LL * LL];      // fp16 exp(scores)        (67 MB)
__device__ float  g_ps [BB * LL * NTILES];  // partial row sums        (2 MB)

// ---------------- helpers ----------------
__device__ __forceinline__ uint32_t smem_u32(const void* p) {
    uint32_t a;
    asm("{ .reg .u64 t; cvta.to.shared.u64 t, %1; cvt.u32.u64 %0, t; }" : "=r"(a) : "l"(p));
    return a;
}
__device__ __forceinline__ void cp_async16(uint32_t dst, const void* src) {
    asm volatile("cp.async.cg.shared.global [%0], [%1], 16;" :: "r"(dst), "l"(src));
}
__device__ __forceinline__ void cp_commit() {
    asm volatile("cp.async.commit_group;" ::: "memory");
}
__device__ __forceinline__ void cp_wait2() {
    asm volatile("cp.async.wait_group 2;" ::: "memory");
}
__device__ __forceinline__ void mma_f16(float* c, const uint32_t* a, const uint32_t* b) {
    asm volatile(
        "mma.sync.aligned.m16n8k16.row.col.f32.f16.f16.f32 "
        "{%0,%1,%2,%3}, {%4,%5,%6,%7}, {%8,%9}, {%0,%1,%2,%3};"
        : "+f"(c[0]), "+f"(c[1]), "+f"(c[2]), "+f"(c[3])
        : "r"(a[0]), "r"(a[1]), "r"(a[2]), "r"(a[3]), "r"(b[0]), "r"(b[1]));
}
__device__ __forceinline__ void ldsm_x4(uint32_t* r, uint32_t addr) {
    asm volatile("ldmatrix.sync.aligned.m8n8.x4.shared.b16 {%0,%1,%2,%3}, [%4];"
        : "=r"(r[0]), "=r"(r[1]), "=r"(r[2]), "=r"(r[3]) : "r"(addr));
}

// ---------------- fp32 -> fp16 conversions ----------------
__global__ void cvt_half(const float* __restrict__ in, __half* __restrict__ out, int n4) {
    int i = blockIdx.x * blockDim.x + threadIdx.x;
    int stride = gridDim.x * blockDim.x;
    const float4* s = (const float4*)in;
    __half2*      d = (__half2*)out;
    for (; i < n4; i += stride) {
        float4 v = s[i];
        d[2 * i]     = __floats2half2_rn(v.x, v.y);
        d[2 * i + 1] = __floats2half2_rn(v.z, v.w);
    }
}
__global__ void cvt_half_w(const float* __restrict__ wq, const float* __restrict__ wk,
                           const float* __restrict__ wv, __half* __restrict__ out) {
    const int n4 = (DD * VV) / 4;
    const float* src = (blockIdx.y == 0) ? wq : (blockIdx.y == 1) ? wk : wv;
    __half2* d = (__half2*)(out + (size_t)blockIdx.y * DD * VV);
    int i = blockIdx.x * blockDim.x + threadIdx.x;
    int stride = gridDim.x * blockDim.x;
    const float4* s = (const float4*)src;
    for (; i < n4; i += stride) {
        float4 v = s[i];
        d[2 * i]     = __floats2half2_rn(v.x, v.y);
        d[2 * i + 1] = __floats2half2_rn(v.z, v.w);
    }
}

// ------- transpose V slice of QKV: [b][l][1024+d] -> Vt[b][d][l], half2 I/O -------
__global__ void transpose_v(const __half* __restrict__ QKV, __half* __restrict__ Vt) {
    __shared__ __half2 s2[64][33];            // [l][d2]
    const __half* Vb = QKV + (size_t)blockIdx.z * LL * NQKV + 2 * DD;
    __half*       Tb = Vt  + (size_t)blockIdx.z * DD * LL;
    const int l0 = blockIdx.x * 64, d0 = blockIdx.y * 64;
    const int tid  = threadIdx.x;
    const int lane = tid & 31, w = tid >> 5;  // 8 warps

#pragma unroll
    for (int it = 0; it < 8; it++) {
        int l = w + 8 * it;
        s2[l][lane] = *(const __half2*)(Vb + (size_t)(l0 + l) * NQKV + d0 + 2 * lane);
    }
    __syncthreads();

#pragma unroll
    for (int it = 0; it < 8; it++) {
        int d  = w + 8 * it;
        int c  = d >> 1;
        __half2 va = s2[2 * lane][c];
        __half2 vb = s2[2 * lane + 1][c];
        __half2 o = (d & 1) ? __halves2half2(__high2half(va), __high2half(vb))
                            : __halves2half2(__low2half(va),  __low2half(vb));
        *(__half2*)(Tb + (size_t)(d0 + d) * LL + l0 + 2 * lane) = o;
    }
}

// ---------------------------------------------------------------------------
// fp16 mma.sync GEMM, NT:  acc[m,n] = sum_k A[m,k] * B[n,k]
// Template: MODE (epilogue), BM (64 or 128). BN=128, BK=64 fixed.
// MODE 0: C fp16 = acc
// MODE 1: C fp16 = exp(acc*alpha); per-row partial sums -> ps  (BM=128 only)
// MODE 2: C fp32 = acc * inv(row); inv from ps partials in prologue
// 256 threads; warp tile (BM/2)x32; 4-stage cp.async, dist 3, one sync/iter.
// BM=64 runs 2 CTAs/SM (96 KB smem, reg cap via launch_bounds).
// ---------------------------------------------------------------------------
#define STAGES 4

template <int MODE, int BM>
__global__ void __launch_bounds__(256, (BM == 64) ? 2 : 1)
gemm_h(const __half* __restrict__ A, const __half* __restrict__ B, void* __restrict__ C,
       float* __restrict__ ps,
       int K, int lda, int ldb, int ldc, long sA, long sB, long sC, float alpha)
{
    constexpr int ATILE = BM * 128;                 // A tile bytes
    constexpr int STAGE_BYTES = ATILE + 16384;      // + B tile (128 rows)
    constexpr int MI = BM / 32;                     // m-frags per warp

    extern __shared__ __align__(1024) char smem[];
    __shared__ float s_inv[BM];
    const uint32_t sbase = smem_u32(smem);

    const int tid  = threadIdx.x;
    const int lane = tid & 31, wid = tid >> 5;
    const int wm = wid >> 2;          // 0..1  (BM/2-row slab)
    const int wn = wid & 3;           // 0..3  (32-col slab)
    const int grp = lane >> 2;        // 0..7
    const int tg  = lane & 3;         // 0..3

    const __half* Ab = A + (long)blockIdx.z * sA;
    const __half* Bb = B + (long)blockIdx.z * sB;
    const int m0 = blockIdx.x * BM;
    const int n0 = blockIdx.y * 128;
    const int T  = K >> 6;

    // MODE 2: finalize 1/rowsum for this CTA's BM rows (fixed add order)
    if (MODE == 2 && tid < BM) {
        const float* p = ps + ((size_t)blockIdx.z * LL + m0 + tid) * NTILES;
        float s = 0.0f;
#pragma unroll
        for (int i = 0; i < NTILES; i++) s += p[i];
        s_inv[tid] = 1.0f / s;
    }

    auto load_stage = [&](int t) {
        const int s  = t % STAGES;
        const int k0 = t << 6;
        const uint32_t st = sbase + s * STAGE_BYTES;
#pragma unroll
        for (int it = 0; it < BM / 32; it++) {      // A: BM rows
            int i   = tid + it * 256;
            int row = i >> 3;
            int ch  = i & 7;
            uint32_t off = (uint32_t)(row * 128) + ((((uint32_t)ch) ^ (row & 7)) << 4);
            cp_async16(st + off, Ab + (size_t)(m0 + row) * lda + k0 + ch * 8);
        }
#pragma unroll
        for (int it = 0; it < 4; it++) {            // B: 128 rows
            int i   = tid + it * 256;
            int row = i >> 3;
            int ch  = i & 7;
            uint32_t off = (uint32_t)(row * 128) + ((((uint32_t)ch) ^ (row & 7)) << 4);
            cp_async16(st + ATILE + off, Bb + (size_t)(n0 + row) * ldb + k0 + ch * 8);
        }
    };

    float c[MI * 4][4];
#pragma unroll
    for (int i = 0; i < MI * 4; i++)
#pragma unroll
        for (int j = 0; j < 4; j++) c[i][j] = 0.0f;

    load_stage(0); cp_commit();
    load_stage(1); cp_commit();
    load_stage(2); cp_commit();

    // --- ldmatrix per-thread invariant addresses ---
    const int sel   = lane >> 3;
    const int rr    = lane & 7;
    const int selhi = sel >> 1, sello = sel & 1;

    uint32_t aRow[MI];                  // A: m0->(r,klo) m1->(r+8,klo) m2->(r,khi) m3->(r+8,khi)
#pragma unroll
    for (int i = 0; i < MI; i++)
        aRow[i] = (uint32_t)((wm * (BM / 2) + i * 16 + (sello << 3) + rr) * 128);
    uint32_t bRow[2];                   // B: m0->(n,klo) m1->(n,khi) m2->(n+8,klo) m3->(n+8,khi)
#pragma unroll
    for (int jj = 0; jj < 2; jj++)
        bRow[jj] = (uint32_t)(ATILE + (wn * 32 + jj * 16 + (selhi << 3) + rr) * 128);

    for (int t = 0; t < T; t++) {
        cp_wait2();
        __syncthreads();                // single barrier per iteration
        if (t + 3 < T) load_stage(t + 3);
        cp_commit();

        const uint32_t sa32 = sbase + (t % STAGES) * STAGE_BYTES;

#pragma unroll
        for (int ks = 0; ks < 4; ks++) {
            const uint32_t achS = ((uint32_t)(2 * ks + selhi) ^ (uint32_t)rr) << 4;
            const uint32_t bchS = ((uint32_t)(2 * ks + sello) ^ (uint32_t)rr) << 4;

            uint32_t a[MI][4];
#pragma unroll
            for (int i = 0; i < MI; i++)
                ldsm_x4(a[i], sa32 + aRow[i] + achS);

            uint32_t b[8];
            ldsm_x4(&b[0], sa32 + bRow[0] + bchS);   // n-frags 0,1
            ldsm_x4(&b[4], sa32 + bRow[1] + bchS);   // n-frags 2,3

#pragma unroll
            for (int i = 0; i < MI; i++)
#pragma unroll
                for (int j = 0; j < 4; j++)
                    mma_f16(c[i * 4 + j], a[i], &b[j * 2]);
        }
    }

    // ---------------- epilogues ----------------
    if (MODE == 2) {
        float* Cb = (float*)C + (long)blockIdx.z * sC;
#pragma unroll
        for (int i = 0; i < MI; i++) {
            int rl = wm * (BM / 2) + i * 16 + grp;
            int r  = m0 + rl;
            float s0 = s_inv[rl];
            float s1 = s_inv[rl + 8];
#pragma unroll
            for (int j = 0; j < 4; j++) {
                int col = n0 + wn * 32 + j * 8 + tg * 2;
                float* cc = c[i * 4 + j];
                *(float2*)&Cb[(size_t)r * ldc + col]       = make_float2(cc[0] * s0, cc[1] * s0);
                *(float2*)&Cb[(size_t)(r + 8) * ldc + col] = make_float2(cc[2] * s1, cc[3] * s1);
            }
        }
    } else if (MODE == 1) {
        __syncthreads();                // smem reuse after last mainloop reads
        __half* Cb = (__half*)C + (long)blockIdx.z * sC;
        float* part = (float*)smem;     // [BM][4] row partials
#pragma unroll
        for (int i = 0; i < MI; i++) {
            int rl = wm * (BM / 2) + i * 16 + grp;
            int r  = m0 + rl;
            float rlo = 0.0f, rhi = 0.0f;
#pragma unroll
            for (int j = 0; j < 4; j++) {
                int col = n0 + wn * 32 + j * 8 + tg * 2;
                float* cc = c[i * 4 + j];
                float v0 = __expf(cc[0] * alpha), v1 = __expf(cc[1] * alpha);
                float v2 = __expf(cc[2] * alpha), v3 = __expf(cc[3] * alpha);
                rlo += v0 + v1; rhi += v2 + v3;
                *(__half2*)&Cb[(size_t)r * ldc + col]       = __floats2half2_rn(v0, v1);
                *(__half2*)&Cb[(size_t)(r + 8) * ldc + col] = __floats2half2_rn(v2, v3);
            }
            rlo += __shfl_xor_sync(0xffffffffu, rlo, 1);
            rlo += __shfl_xor_sync(0xffffffffu, rlo, 2);
            rhi += __shfl_xor_sync(0xffffffffu, rhi, 1);
            rhi += __shfl_xor_sync(0xffffffffu, rhi, 2);
            if (tg == 0) {
                part[rl * 4 + wn]       = rlo;
                part[(rl + 8) * 4 + wn] = rhi;
            }
        }
        __syncthreads();
        if (tid < BM) {
            float s = part[tid * 4] + part[tid * 4 + 1] + part[tid * 4 + 2] + part[tid * 4 + 3];
            ps[((size_t)blockIdx.z * LL + m0 + tid) * NTILES + blockIdx.y] = s;
        }
    } else {
        __half* Cb = (__half*)C + (long)blockIdx.z * sC;
#pragma unroll
        for (int i = 0; i < MI; i++) {
            int r = m0 + wm * (BM / 2) + i * 16 + grp;
#pragma unroll
            for (int j = 0; j < 4; j++) {
                int col = n0 + wn * 32 + j * 8 + tg * 2;
                float* cc = c[i * 4 + j];
                *(__half2*)&Cb[(size_t)r * ldc + col]       = __floats2half2_rn(cc[0], cc[1]);
                *(__half2*)&Cb[(size_t)(r + 8) * ldc + col] = __floats2half2_rn(cc[2], cc[3]);
            }
        }
    }
}

// ---------------------------------------------------------------------------
extern "C" void kernel_launch(void* const* d_in, const int* in_sizes, int n_in,
                              void* d_out, int out_size)
{
    (void)in_sizes; (void)n_in; (void)out_size;
    const float* x  = (const float*)d_in[0];   // [B, L, V]
    const float* Wq = (const float*)d_in[1];   // [D, V]
    const float* Wk = (const float*)d_in[2];
    const float* Wv = (const float*)d_in[3];
    float* out = (float*)d_out;                // [B, L, D]

    __half *xh, *wh, *qkv, *vt, *ep;
    float *psp;
    cudaGetSymbolAddress((void**)&xh,  g_Xh);
    cudaGetSymbolAddress((void**)&wh,  g_Wh);
    cudaGetSymbolAddress((void**)&qkv, g_QKV);
    cudaGetSymbolAddress((void**)&vt,  g_Vt);
    cudaGetSymbolAddress((void**)&ep,  g_E);
    cudaGetSymbolAddress((void**)&psp, g_ps);

    constexpr int SMEM64  = (64 + 128) * 128 * STAGES;    // 98304
    constexpr int SMEM128 = (128 + 128) * 128 * STAGES;   // 131072
    cudaFuncSetAttribute((const void*)gemm_h<0, 64>,  cudaFuncAttributeMaxDynamicSharedMemorySize, SMEM64);
    cudaFuncSetAttribute((const void*)gemm_h<1, 128>, cudaFuncAttributeMaxDynamicSharedMemorySize, SMEM128);
    cudaFuncSetAttribute((const void*)gemm_h<2, 64>,  cudaFuncAttributeMaxDynamicSharedMemorySize, SMEM64);

    // 0) fp32 -> fp16
    cvt_half<<<2048, 256>>>(x, xh, (BB * LL * VV) / 4);
    cvt_half_w<<<dim3(128, 3), 256>>>(Wq, Wk, Wv, wh);

    // 1) fused QKV projection -> fp16 [16384,1536]   (BM=64: 3072 CTAs, 2/SM)
    {
        dim3 g(BB * LL / 64, NQKV / 128, 1);
        gemm_h<0, 64><<<g, 256, SMEM64>>>(xh, wh, qkv, nullptr,
                                          VV, VV, VV, NQKV, 0, 0, 0, 1.0f);
    }

    // 2) V slice -> Vt [b][d][l]
    transpose_v<<<dim3(LL / 64, DD / 64, BB), 256>>>(qkv, vt);

    // 3) E = exp(Q K^T / sqrt(D)) fp16, fused partial row sums (BM=128)
    {
        dim3 g(LL / 128, LL / 128, BB);
        gemm_h<1, 128><<<g, 256, SMEM128>>>(qkv, qkv + DD, ep, psp,
                                            DD, NQKV, NQKV, LL,
                                            (long)LL * NQKV, (long)LL * NQKV, (long)LL * LL,
                                            0.044194173824159216f);
    }

    // 4) O = (E V) * inv — rowsum finalize fused in prologue (BM=64: 1024 CTAs)
    {
        dim3 g(LL / 64, DD / 128, BB);
        gemm_h<2, 64><<<g, 256, SMEM64>>>(ep, vt, out, psp,
                                          LL, LL, LL, DD,
                                          (long)LL * LL, (long)DD * LL, (long)LL * DD,
                                          1.0f);
    }
}

// round 14
// speedup vs baseline: 4.8462x; 1.0325x over previous
#include <cuda_runtime.h>
#include <cuda_fp16.h>
#include <cstdint>

#define BB 8
#define LL 2048
#define VV 1024
#define DD 512
#define NQKV 1536            // 3*DD concatenated
#define NTILES (LL / 128)    // 16 n-tiles in scores GEMM

// ---------------- scratch (device globals; no allocs allowed) ----------------
__device__ __half g_Xh [BB * LL * VV];      // fp16 x                  (34 MB)
__device__ __half g_Wh [NQKV * VV];         // fp16 [Wq;Wk;Wv]         (3 MB)
__device__ __half g_QKV[BB * LL * NQKV];    // fp16 Q|K|V interleaved  (50 MB)
__device__ __half g_E  [BB * LL * LL];      // fp16 exp(scores)        (67 MB)
__device__ float  g_ps [BB * LL * NTILES];  // partial row sums        (2 MB)

// ---------------- helpers ----------------
__device__ __forceinline__ uint32_t smem_u32(const void* p) {
    uint32_t a;
    asm("{ .reg .u64 t; cvta.to.shared.u64 t, %1; cvt.u32.u64 %0, t; }" : "=r"(a) : "l"(p));
    return a;
}
__device__ __forceinline__ void cp_async16(uint32_t dst, const void* src) {
    asm volatile("cp.async.cg.shared.global [%0], [%1], 16;" :: "r"(dst), "l"(src));
}
__device__ __forceinline__ void cp_commit() {
    asm volatile("cp.async.commit_group;" ::: "memory");
}
__device__ __forceinline__ void cp_wait2() {
    asm volatile("cp.async.wait_group 2;" ::: "memory");
}
__device__ __forceinline__ void mma_f16(float* c, const uint32_t* a, const uint32_t* b) {
    asm volatile(
        "mma.sync.aligned.m16n8k16.row.col.f32.f16.f16.f32 "
        "{%0,%1,%2,%3}, {%4,%5,%6,%7}, {%8,%9}, {%0,%1,%2,%3};"
        : "+f"(c[0]), "+f"(c[1]), "+f"(c[2]), "+f"(c[3])
        : "r"(a[0]), "r"(a[1]), "r"(a[2]), "r"(a[3]), "r"(b[0]), "r"(b[1]));
}
__device__ __forceinline__ void ldsm_x4(uint32_t* r, uint32_t addr) {
    asm volatile("ldmatrix.sync.aligned.m8n8.x4.shared.b16 {%0,%1,%2,%3}, [%4];"
        : "=r"(r[0]), "=r"(r[1]), "=r"(r[2]), "=r"(r[3]) : "r"(addr));
}
__device__ __forceinline__ void ldsm_x4_trans(uint32_t* r, uint32_t addr) {
    asm volatile("ldmatrix.sync.aligned.m8n8.x4.trans.shared.b16 {%0,%1,%2,%3}, [%4];"
        : "=r"(r[0]), "=r"(r[1]), "=r"(r[2]), "=r"(r[3]) : "r"(addr));
}

// ---------------- fused fp32 -> fp16 conversion (x + 3 weights, one launch) ----------------
__global__ void __launch_bounds__(256)
cvt_all(const float* __restrict__ x,
        const float* __restrict__ wq, const float* __restrict__ wk,
        const float* __restrict__ wv,
        __half* __restrict__ xh, __half* __restrict__ wh)
{
    int b = blockIdx.x;
    const float* src; __half2* dst; int n4, base, stride;
    if (b < 2048) {                       // x: 16.8M floats
        src = x; dst = (__half2*)xh;
        n4 = (BB * LL * VV) / 4; base = b * 256 + threadIdx.x; stride = 2048 * 256;
    } else {                              // weights: 3 x 512K floats
        b -= 2048;
        int w = b >> 7, blk = b & 127;    // 128 blocks per weight
        src = (w == 0) ? wq : (w == 1) ? wk : wv;
        dst = (__half2*)(wh + (size_t)w * DD * VV);
        n4 = (DD * VV) / 4; base = blk * 256 + threadIdx.x; stride = 128 * 256;
    }
    const float4* s = (const float4*)src;
    for (int i = base; i < n4; i += stride) {
        float4 v = s[i];
        dst[2 * i]     = __floats2half2_rn(v.x, v.y);
        dst[2 * i + 1] = __floats2half2_rn(v.z, v.w);
    }
}

// ---------------------------------------------------------------------------
// fp16 mma.sync GEMM, NT:  acc[m,n] = sum_k A[m,k] * B[n,k]
// Template: MODE (epilogue), BM (64/128), TRANSB.
// TRANSB=false: B stored [N,K] k-major, 128B rows, non-trans ldmatrix.
// TRANSB=true : B stored [K,N] n-major (256B rows of 128 cols, ld=ldb elems),
//               loaded with ldmatrix.x4.trans -> identical fragments.
// MODE 0: C fp16 = acc
// MODE 1: C fp16 = exp(acc*alpha); per-row partial sums -> ps  (BM=128)
// MODE 2: C fp32 = acc * inv(row); inv from ps partials in prologue
// 256 threads; warp tile (BM/2)x32; 4-stage cp.async, dist 3, one sync/iter.
// ---------------------------------------------------------------------------
#define STAGES 4

template <int MODE, int BM, bool TRANSB>
__global__ void __launch_bounds__(256, (BM == 64) ? 2 : 1)
gemm_h(const __half* __restrict__ A, const __half* __restrict__ B, void* __restrict__ C,
       float* __restrict__ ps,
       int K, int lda, int ldb, int ldc, long sA, long sB, long sC, float alpha)
{
    constexpr int ATILE = BM * 128;                 // A tile bytes
    constexpr int STAGE_BYTES = ATILE + 16384;      // + B tile (16 KB both layouts)
    constexpr int MI = BM / 32;                     // m-frags per warp

    extern __shared__ __align__(1024) char smem[];
    __shared__ float s_inv[BM];
    const uint32_t sbase = smem_u32(smem);

    const int tid  = threadIdx.x;
    const int lane = tid & 31, wid = tid >> 5;
    const int wm = wid >> 2;          // 0..1  (BM/2-row slab)
    const int wn = wid & 3;           // 0..3  (32-col slab)
    const int grp = lane >> 2;        // 0..7
    const int tg  = lane & 3;         // 0..3

    const __half* Ab = A + (long)blockIdx.z * sA;
    const __half* Bb = B + (long)blockIdx.z * sB;
    const int m0 = blockIdx.x * BM;
    const int n0 = blockIdx.y * 128;
    const int T  = K >> 6;

    // MODE 2: finalize 1/rowsum for this CTA's BM rows (fixed add order)
    if (MODE == 2 && tid < BM) {
        const float* p = ps + ((size_t)blockIdx.z * LL + m0 + tid) * NTILES;
        float s = 0.0f;
#pragma unroll
        for (int i = 0; i < NTILES; i++) s += p[i];
        s_inv[tid] = 1.0f / s;
    }

    auto load_stage = [&](int t) {
        const int s  = t % STAGES;
        const int k0 = t << 6;
        const uint32_t st = sbase + s * STAGE_BYTES;
#pragma unroll
        for (int it = 0; it < BM / 32; it++) {      // A: BM rows, 128B each
            int i   = tid + it * 256;
            int row = i >> 3;
            int ch  = i & 7;
            uint32_t off = (uint32_t)(row * 128) + ((((uint32_t)ch) ^ (row & 7)) << 4);
            cp_async16(st + off, Ab + (size_t)(m0 + row) * lda + k0 + ch * 8);
        }
        if (TRANSB) {                               // B: 64 k-rows x 256B (128 n-cols)
#pragma unroll
            for (int it = 0; it < 4; it++) {
                int i   = tid + it * 256;           // 0..1023
                int row = i >> 4;                   // 0..63 (k)
                int ch  = i & 15;                   // 16B chunk (8 n)
                uint32_t off = (uint32_t)(row * 256) + ((((uint32_t)ch) ^ (row & 7)) << 4);
                cp_async16(st + ATILE + off, Bb + (size_t)(k0 + row) * ldb + n0 + ch * 8);
            }
        } else {                                    // B: 128 n-rows x 128B
#pragma unroll
            for (int it = 0; it < 4; it++) {
                int i   = tid + it * 256;
                int row = i >> 3;
                int ch  = i & 7;
                uint32_t off = (uint32_t)(row * 128) + ((((uint32_t)ch) ^ (row & 7)) << 4);
                cp_async16(st + ATILE + off, Bb + (size_t)(n0 + row) * ldb + k0 + ch * 8);
            }
        }
    };

    float c[MI * 4][4];
#pragma unroll
    for (int i = 0; i < MI * 4; i++)
#pragma unroll
        for (int j = 0; j < 4; j++) c[i][j] = 0.0f;

    load_stage(0); cp_commit();
    load_stage(1); cp_commit();
    load_stage(2); cp_commit();

    // --- ldmatrix per-thread invariant addresses ---
    const int sel   = lane >> 3;
    const int rr    = lane & 7;
    const int selhi = sel >> 1, sello = sel & 1;

    uint32_t aRow[MI];                  // A: m0->(r,klo) m1->(r+8,klo) m2->(r,khi) m3->(r+8,khi)
#pragma unroll
    for (int i = 0; i < MI; i++)
        aRow[i] = (uint32_t)((wm * (BM / 2) + i * 16 + (sello << 3) + rr) * 128);

    // non-trans B
    uint32_t bRow[2];
#pragma unroll
    for (int jj = 0; jj < 2; jj++)
        bRow[jj] = (uint32_t)(ATILE + (wn * 32 + jj * 16 + (selhi << 3) + rr) * 128);
    // trans B: matrices q={klo n0-7, khi n0-7, klo n8-15, khi n8-15} per j-pair
    uint32_t bT[2];
    {
        const int rb  = (sello << 3) + rr;          // k-row low bits (row&7 == rr)
        const int chb = selhi;                      // n 8-col half
#pragma unroll
        for (int p = 0; p < 2; p++) {
            int chunk = wn * 4 + p * 2 + chb;
            bT[p] = (uint32_t)(ATILE + rb * 256 + ((chunk ^ rr) << 4));
        }
    }

    for (int t = 0; t < T; t++) {
        cp_wait2();
        __syncthreads();                // single barrier per iteration
        if (t + 3 < T) load_stage(t + 3);
        cp_commit();

        const uint32_t sa32 = sbase + (t % STAGES) * STAGE_BYTES;

#pragma unroll
        for (int ks = 0; ks < 4; ks++) {
            const uint32_t achS = ((uint32_t)(2 * ks + selhi) ^ (uint32_t)rr) << 4;

            uint32_t a[MI][4];
#pragma unroll
            for (int i = 0; i < MI; i++)
                ldsm_x4(a[i], sa32 + aRow[i] + achS);

            uint32_t b[8];
            if (TRANSB) {
                ldsm_x4_trans(&b[0], sa32 + bT[0] + ks * 4096);  // n-frags 0,1
                ldsm_x4_trans(&b[4], sa32 + bT[1] + ks * 4096);  // n-frags 2,3
            } else {
                const uint32_t bchS = ((uint32_t)(2 * ks + sello) ^ (uint32_t)rr) << 4;
                ldsm_x4(&b[0], sa32 + bRow[0] + bchS);
                ldsm_x4(&b[4], sa32 + bRow[1] + bchS);
            }

#pragma unroll
            for (int i = 0; i < MI; i++)
#pragma unroll
                for (int j = 0; j < 4; j++)
                    mma_f16(c[i * 4 + j], a[i], &b[j * 2]);
        }
    }

    // ---------------- epilogues ----------------
    if (MODE == 2) {
        float* Cb = (float*)C + (long)blockIdx.z * sC;
#pragma unroll
        for (int i = 0; i < MI; i++) {
            int rl = wm * (BM / 2) + i * 16 + grp;
            int r  = m0 + rl;
            float s0 = s_inv[rl];
            float s1 = s_inv[rl + 8];
#pragma unroll
            for (int j = 0; j < 4; j++) {
                int col = n0 + wn * 32 + j * 8 + tg * 2;
                float* cc = c[i * 4 + j];
                *(float2*)&Cb[(size_t)r * ldc + col]       = make_float2(cc[0] * s0, cc[1] * s0);
                *(float2*)&Cb[(size_t)(r + 8) * ldc + col] = make_float2(cc[2] * s1, cc[3] * s1);
            }
        }
    } else if (MODE == 1) {
        __syncthreads();                // smem reuse after last mainloop reads
        __half* Cb = (__half*)C + (long)blockIdx.z * sC;
        float* part = (float*)smem;     // [BM][4] row partials
#pragma unroll
        for (int i = 0; i < MI; i++) {
            int rl = wm * (BM / 2) + i * 16 + grp;
            int r  = m0 + rl;
            float rlo = 0.0f, rhi = 0.0f;
#pragma unroll
            for (int j = 0; j < 4; j++) {
                int col = n0 + wn * 32 + j * 8 + tg * 2;
                float* cc = c[i * 4 + j];
                float v0 = __expf(cc[0] * alpha), v1 = __expf(cc[1] * alpha);
                float v2 = __expf(cc[2] * alpha), v3 = __expf(cc[3] * alpha);
                rlo += v0 + v1; rhi += v2 + v3;
                *(__half2*)&Cb[(size_t)r * ldc + col]       = __floats2half2_rn(v0, v1);
                *(__half2*)&Cb[(size_t)(r + 8) * ldc + col] = __floats2half2_rn(v2, v3);
            }
            rlo += __shfl_xor_sync(0xffffffffu, rlo, 1);
            rlo += __shfl_xor_sync(0xffffffffu, rlo, 2);
            rhi += __shfl_xor_sync(0xffffffffu, rhi, 1);
            rhi += __shfl_xor_sync(0xffffffffu, rhi, 2);
            if (tg == 0) {
                part[rl * 4 + wn]       = rlo;
                part[(rl + 8) * 4 + wn] = rhi;
            }
        }
        __syncthreads();
        if (tid < BM) {
            float s = part[tid * 4] + part[tid * 4 + 1] + part[tid * 4 + 2] + part[tid * 4 + 3];
            ps[((size_t)blockIdx.z * LL + m0 + tid) * NTILES + blockIdx.y] = s;
        }
    } else {
        __half* Cb = (__half*)C + (long)blockIdx.z * sC;
#pragma unroll
        for (int i = 0; i < MI; i++) {
            int r = m0 + wm * (BM / 2) + i * 16 + grp;
#pragma unroll
            for (int j = 0; j < 4; j++) {
                int col = n0 + wn * 32 + j * 8 + tg * 2;
                float* cc = c[i * 4 + j];
                *(__half2*)&Cb[(size_t)r * ldc + col]       = __floats2half2_rn(cc[0], cc[1]);
                *(__half2*)&Cb[(size_t)(r + 8) * ldc + col] = __floats2half2_rn(cc[2], cc[3]);
            }
        }
    }
}

// ---------------------------------------------------------------------------
extern "C" void kernel_launch(void* const* d_in, const int* in_sizes, int n_in,
                              void* d_out, int out_size)
{
    (void)in_sizes; (void)n_in; (void)out_size;
    const float* x  = (const float*)d_in[0];   // [B, L, V]
    const float* Wq = (const float*)d_in[1];   // [D, V]
    const float* Wk = (const float*)d_in[2];
    const float* Wv = (const float*)d_in[3];
    float* out = (float*)d_out;                // [B, L, D]

    __half *xh, *wh, *qkv, *ep;
    float *psp;
    cudaGetSymbolAddress((void**)&xh,  g_Xh);
    cudaGetSymbolAddress((void**)&wh,  g_Wh);
    cudaGetSymbolAddress((void**)&qkv, g_QKV);
    cudaGetSymbolAddress((void**)&ep,  g_E);
    cudaGetSymbolAddress((void**)&psp, g_ps);

    constexpr int SMEM64  = (64 + 128) * 128 * STAGES;    // 98304
    constexpr int SMEM128 = (128 + 128) * 128 * STAGES;   // 131072
    cudaFuncSetAttribute((const void*)gemm_h<0, 64, false>,  cudaFuncAttributeMaxDynamicSharedMemorySize, SMEM64);
    cudaFuncSetAttribute((const void*)gemm_h<1, 128, false>, cudaFuncAttributeMaxDynamicSharedMemorySize, SMEM128);
    cudaFuncSetAttribute((const void*)gemm_h<2, 64, true>,   cudaFuncAttributeMaxDynamicSharedMemorySize, SMEM64);

    // 0) fp32 -> fp16 (x + weights, one launch)
    cvt_all<<<2048 + 3 * 128, 256>>>(x, Wq, Wk, Wv, xh, wh);

    // 1) fused QKV projection -> fp16 [16384,1536]   (BM=64: 3072 CTAs, 2/SM)
    {
        dim3 g(BB * LL / 64, NQKV / 128, 1);
        gemm_h<0, 64, false><<<g, 256, SMEM64>>>(xh, wh, qkv, nullptr,
                                                 VV, VV, VV, NQKV, 0, 0, 0, 1.0f);
    }

    // 2) E = exp(Q K^T / sqrt(D)) fp16, fused partial row sums (BM=128)
    {
        dim3 g(LL / 128, LL / 128, BB);
        gemm_h<1, 128, false><<<g, 256, SMEM128>>>(qkv, qkv + DD, ep, psp,
                                                   DD, NQKV, NQKV, LL,
                                                   (long)LL * NQKV, (long)LL * NQKV, (long)LL * LL,
                                                   0.044194173824159216f);
    }

    // 3) O = (E V) * inv — V read in-place via ldmatrix.trans (no transpose pass)
    {
        dim3 g(LL / 64, DD / 128, BB);
        gemm_h<2, 64, true><<<g, 256, SMEM64>>>(ep, qkv + 2 * DD, out, psp,
                                                LL, LL, NQKV, DD,
                                                (long)LL * LL, (long)LL * NQKV, (long)LL * DD,
                                                1.0f);
    }
}